// round 1
// baseline (speedup 1.0000x reference)
#include <cuda_runtime.h>
#include <math.h>

#define NHEAD 16
#define DK 64
#define DMODEL 1024
#define BATCH 4
#define SEQ 2048
#define MTOT (BATCH*SEQ)   // 8192

// Scratch: projected q/k/v in [B,H,S,DK] layout, attention output in [B,S,DMODEL]
__device__ float g_q[(size_t)BATCH*NHEAD*SEQ*DK];
__device__ float g_k[(size_t)BATCH*NHEAD*SEQ*DK];
__device__ float g_v[(size_t)BATCH*NHEAD*SEQ*DK];
__device__ float g_x[(size_t)MTOT*DMODEL];

// ---------------------------------------------------------------------------
// GEMM: C = A @ W^T + bias.  A:[M,1024] row-major, W:[1024,1024] row-major
// (so both operands are K-contiguous).  128x128x16 tile, 256 threads,
// 8x8 per-thread micro-tile (split as 4+4 in each dim for conflict-free LDS.128).
// outSel: 0->g_q 1->g_k 2->g_v (head-split layout), 3->Cout (plain [M,N]).
// ---------------------------------------------------------------------------
#define BM 128
#define BN 128
#define BKD 16
#define GST (BM + 4)   // smem row stride (floats); 132*4B = 528B, 16B-aligned

__global__ __launch_bounds__(256, 2)
void gemm_bias_kernel(const float* __restrict__ Ain,
                      const float* __restrict__ W,
                      const float* __restrict__ bias,
                      float* __restrict__ Cout,
                      int outSel)
{
    const float* A = Ain ? Ain : g_x;
    float* C;
    int split;
    if      (outSel == 0) { C = g_q;  split = 1; }
    else if (outSel == 1) { C = g_k;  split = 1; }
    else if (outSel == 2) { C = g_v;  split = 1; }
    else                  { C = Cout; split = 0; }

    __shared__ float As[BKD][GST];
    __shared__ float Ws[BKD][GST];

    const int tid = threadIdx.x;
    const int bm = blockIdx.y * BM;
    const int bn = blockIdx.x * BN;

    // global->smem loader mapping: each thread loads 2 float4 of A and 2 of W
    const int lr = tid >> 2;          // 0..63
    const int lc = (tid & 3) << 2;    // 0,4,8,12

    // compute mapping: rows tm..tm+3 and tm+64..tm+67; cols tn.., tn+64..
    const int tm = (tid >> 4) << 2;   // 0..60
    const int tn = (tid & 15) << 2;   // 0..60

    float acc[8][8];
#pragma unroll
    for (int i = 0; i < 8; i++)
#pragma unroll
        for (int j = 0; j < 8; j++) acc[i][j] = 0.f;

    const float* Aptr = A + (size_t)(bm + lr) * DMODEL + lc;
    const float* Wptr = W + (size_t)(bn + lr) * DMODEL + lc;

    for (int k0 = 0; k0 < DMODEL; k0 += BKD) {
        float4 a0 = *(const float4*)(Aptr + k0);
        float4 a1 = *(const float4*)(Aptr + k0 + (size_t)64 * DMODEL);
        float4 w0 = *(const float4*)(Wptr + k0);
        float4 w1 = *(const float4*)(Wptr + k0 + (size_t)64 * DMODEL);

        As[lc + 0][lr] = a0.x; As[lc + 1][lr] = a0.y;
        As[lc + 2][lr] = a0.z; As[lc + 3][lr] = a0.w;
        As[lc + 0][lr + 64] = a1.x; As[lc + 1][lr + 64] = a1.y;
        As[lc + 2][lr + 64] = a1.z; As[lc + 3][lr + 64] = a1.w;
        Ws[lc + 0][lr] = w0.x; Ws[lc + 1][lr] = w0.y;
        Ws[lc + 2][lr] = w0.z; Ws[lc + 3][lr] = w0.w;
        Ws[lc + 0][lr + 64] = w1.x; Ws[lc + 1][lr + 64] = w1.y;
        Ws[lc + 2][lr + 64] = w1.z; Ws[lc + 3][lr + 64] = w1.w;

        __syncthreads();

#pragma unroll
        for (int kk = 0; kk < BKD; kk++) {
            float4 av0 = *(const float4*)&As[kk][tm];
            float4 av1 = *(const float4*)&As[kk][tm + 64];
            float4 wv0 = *(const float4*)&Ws[kk][tn];
            float4 wv1 = *(const float4*)&Ws[kk][tn + 64];
            float a[8] = {av0.x, av0.y, av0.z, av0.w, av1.x, av1.y, av1.z, av1.w};
            float w[8] = {wv0.x, wv0.y, wv0.z, wv0.w, wv1.x, wv1.y, wv1.z, wv1.w};
#pragma unroll
            for (int i = 0; i < 8; i++)
#pragma unroll
                for (int j = 0; j < 8; j++)
                    acc[i][j] += a[i] * w[j];
        }
        __syncthreads();
    }

    // epilogue
#pragma unroll
    for (int i = 0; i < 8; i++) {
        int rofs = (i < 4) ? i : (64 + i - 4);
        int m = bm + tm + rofs;
        int b = m >> 11;            // /SEQ
        int s = m & (SEQ - 1);
#pragma unroll
        for (int j = 0; j < 8; j++) {
            int cofs = (j < 4) ? j : (64 + j - 4);
            int n = bn + tn + cofs;
            float val = acc[i][j] + bias[n];
            if (split) {
                int h = n >> 6;
                int d = n & 63;
                C[((((size_t)b * NHEAD + h) * SEQ) + s) * DK + d] = val;
            } else {
                C[(size_t)m * DMODEL + n] = val;
            }
        }
    }
}

// ---------------------------------------------------------------------------
// Flash attention: per (b,h), 64 query rows per block, stream KV in 64-row
// tiles. 256 threads as 16x16; 4x4 register tiles in both score and PV phases.
// Online softmax (row state replicated across the 16 threads sharing a row;
// reductions via shfl_xor across 16 lanes).
// ---------------------------------------------------------------------------
#define BQ 64
#define BKT 64
#define QST 65   // smem row stride (odd -> avoids 16-way K-row bank conflicts)
#define ATTN_SMEM_BYTES ((BQ*QST + 2*BKT*QST + BQ*QST) * 4)

__global__ __launch_bounds__(256, 1)
void attn_kernel()
{
    extern __shared__ float sm[];
    float* Qs = sm;                    // [BQ][QST]
    float* Ks = Qs + BQ * QST;         // [BKT][QST]
    float* Vs = Ks + BKT * QST;        // [BKT][QST]
    float* Ps = Vs + BKT * QST;        // [BQ][QST]

    const int tid = threadIdx.x;
    const int bh = blockIdx.y;           // b*NHEAD + h
    const int q0 = blockIdx.x * BQ;
    const int b = bh >> 4;
    const int h = bh & (NHEAD - 1);

    const float* Q = g_q + (size_t)bh * SEQ * DK;
    const float* K = g_k + (size_t)bh * SEQ * DK;
    const float* V = g_v + (size_t)bh * SEQ * DK;

    // load Q tile (64x64 floats = 1024 float4)
    for (int i = tid; i < BQ * DK / 4; i += 256) {
        int r = i >> 4;
        int c = (i & 15) << 2;
        float4 v4 = *(const float4*)&Q[(size_t)(q0 + r) * DK + c];
        float* dst = &Qs[r * QST + c];
        dst[0] = v4.x; dst[1] = v4.y; dst[2] = v4.z; dst[3] = v4.w;
    }

    const int ty = tid >> 4;   // 0..15 -> query rows ty*4..+3
    const int tx = tid & 15;   // 0..15 -> key cols / d cols tx*4..+3

    float m_i[4], l_i[4], o_acc[4][4];
#pragma unroll
    for (int i = 0; i < 4; i++) {
        m_i[i] = -INFINITY;
        l_i[i] = 0.f;
#pragma unroll
        for (int j = 0; j < 4; j++) o_acc[i][j] = 0.f;
    }

    for (int kt = 0; kt < SEQ; kt += BKT) {
        __syncthreads();   // previous tile's Ps/Vs reads done; Q tile visible (1st iter)

        // load K,V tiles
        for (int i = tid; i < BKT * DK / 4; i += 256) {
            int r = i >> 4;
            int c = (i & 15) << 2;
            float4 kv = *(const float4*)&K[(size_t)(kt + r) * DK + c];
            float4 vv = *(const float4*)&V[(size_t)(kt + r) * DK + c];
            float* kd = &Ks[r * QST + c];
            kd[0] = kv.x; kd[1] = kv.y; kd[2] = kv.z; kd[3] = kv.w;
            float* vd = &Vs[r * QST + c];
            vd[0] = vv.x; vd[1] = vv.y; vd[2] = vv.z; vd[3] = vv.w;
        }
        __syncthreads();

        // scores: s[i][j] = Q[ty*4+i] . K[tx*4+j]
        float s[4][4];
#pragma unroll
        for (int i = 0; i < 4; i++)
#pragma unroll
            for (int j = 0; j < 4; j++) s[i][j] = 0.f;

#pragma unroll 8
        for (int d = 0; d < DK; d++) {
            float qv[4], kv[4];
#pragma unroll
            for (int i = 0; i < 4; i++) qv[i] = Qs[(ty * 4 + i) * QST + d];
#pragma unroll
            for (int j = 0; j < 4; j++) kv[j] = Ks[(tx * 4 + j) * QST + d];
#pragma unroll
            for (int i = 0; i < 4; i++)
#pragma unroll
                for (int j = 0; j < 4; j++)
                    s[i][j] += qv[i] * kv[j];
        }

        // online softmax update + write P tile
        const float scale = 0.125f;   // 1/sqrt(64)
#pragma unroll
        for (int i = 0; i < 4; i++) {
            float mx = -INFINITY;
#pragma unroll
            for (int j = 0; j < 4; j++) {
                s[i][j] *= scale;
                mx = fmaxf(mx, s[i][j]);
            }
#pragma unroll
            for (int off = 8; off > 0; off >>= 1)
                mx = fmaxf(mx, __shfl_xor_sync(0xffffffffu, mx, off));

            float mnew = fmaxf(m_i[i], mx);
            float alpha = __expf(m_i[i] - mnew);
            m_i[i] = mnew;

            float rs = 0.f;
#pragma unroll
            for (int j = 0; j < 4; j++) {
                s[i][j] = __expf(s[i][j] - mnew);
                rs += s[i][j];
            }
#pragma unroll
            for (int off = 8; off > 0; off >>= 1)
                rs += __shfl_xor_sync(0xffffffffu, rs, off);

            l_i[i] = l_i[i] * alpha + rs;
#pragma unroll
            for (int j = 0; j < 4; j++) o_acc[i][j] *= alpha;

            float* pd = &Ps[(ty * 4 + i) * QST + tx * 4];
            pd[0] = s[i][0]; pd[1] = s[i][1]; pd[2] = s[i][2]; pd[3] = s[i][3];
        }
        __syncthreads();

        // O += P @ V   (o cols = d dimension, tx*4..+3)
#pragma unroll 8
        for (int c = 0; c < BKT; c++) {
            float pf[4], vf[4];
#pragma unroll
            for (int i = 0; i < 4; i++) pf[i] = Ps[(ty * 4 + i) * QST + c];
#pragma unroll
            for (int j = 0; j < 4; j++) vf[j] = Vs[c * QST + tx * 4 + j];
#pragma unroll
            for (int i = 0; i < 4; i++)
#pragma unroll
                for (int j = 0; j < 4; j++)
                    o_acc[i][j] += pf[i] * vf[j];
        }
    }

    // write output in [B,S,H*DK] layout
#pragma unroll
    for (int i = 0; i < 4; i++) {
        float inv = 1.0f / l_i[i];
        int srow = q0 + ty * 4 + i;
        float4 o4;
        o4.x = o_acc[i][0] * inv;
        o4.y = o_acc[i][1] * inv;
        o4.z = o_acc[i][2] * inv;
        o4.w = o_acc[i][3] * inv;
        *(float4*)&g_x[((size_t)(b * SEQ + srow)) * DMODEL + h * DK + tx * 4] = o4;
    }
}

// ---------------------------------------------------------------------------
// Launch: Q/K/V projections -> attention -> output projection.
// Input order (metadata): query, key, value, Wq, bq, Wk, bk, Wv, bv, Wo, bo.
// ---------------------------------------------------------------------------
extern "C" void kernel_launch(void* const* d_in, const int* in_sizes, int n_in,
                              void* d_out, int out_size)
{
    (void)in_sizes; (void)n_in; (void)out_size;
    const float* query = (const float*)d_in[0];
    const float* key   = (const float*)d_in[1];
    const float* value = (const float*)d_in[2];
    const float* Wq = (const float*)d_in[3];
    const float* bq = (const float*)d_in[4];
    const float* Wk = (const float*)d_in[5];
    const float* bk = (const float*)d_in[6];
    const float* Wv = (const float*)d_in[7];
    const float* bv = (const float*)d_in[8];
    const float* Wo = (const float*)d_in[9];
    const float* bo = (const float*)d_in[10];
    float* out = (float*)d_out;

    // idempotent; needed for 65KB dynamic smem
    cudaFuncSetAttribute(attn_kernel,
                         cudaFuncAttributeMaxDynamicSharedMemorySize,
                         ATTN_SMEM_BYTES);

    dim3 ggrid(DMODEL / BN, MTOT / BM);   // (8, 64)
    gemm_bias_kernel<<<ggrid, 256>>>(query, Wq, bq, nullptr, 0);
    gemm_bias_kernel<<<ggrid, 256>>>(key,   Wk, bk, nullptr, 1);
    gemm_bias_kernel<<<ggrid, 256>>>(value, Wv, bv, nullptr, 2);

    attn_kernel<<<dim3(SEQ / BQ, BATCH * NHEAD), 256, ATTN_SMEM_BYTES>>>();

    gemm_bias_kernel<<<ggrid, 256>>>(nullptr, Wo, bo, out, 3);
}

// round 3
// speedup vs baseline: 2.7927x; 2.7927x over previous
#include <cuda_runtime.h>
#include <cuda_bf16.h>
#include <math.h>
#include <stdint.h>

#define NHEAD 16
#define DK 64
#define DMODEL 1024
#define BATCH 4
#define SEQ 2048
#define MTOT (BATCH*SEQ)   // 8192
#define HS ((size_t)BATCH*NHEAD*SEQ*DK)   // 8.39M

// ---------------- scratch ----------------
__device__ __nv_bfloat16 g_ah[(size_t)MTOT*DMODEL];
__device__ __nv_bfloat16 g_al[(size_t)MTOT*DMODEL];
__device__ __nv_bfloat16 g_wh[(size_t)DMODEL*DMODEL];
__device__ __nv_bfloat16 g_wl[(size_t)DMODEL*DMODEL];
__device__ __nv_bfloat16 g_qh[HS], g_ql[HS];
__device__ __nv_bfloat16 g_kh[HS], g_kl[HS];
__device__ __nv_bfloat16 g_vh[HS], g_vl[HS];

// ---------------- helpers ----------------
__device__ __forceinline__ uint32_t smem_u32(const void* p) {
    uint32_t a;
    asm("{ .reg .u64 t; cvta.to.shared.u64 t, %1; cvt.u32.u64 %0, t; }" : "=r"(a) : "l"(p));
    return a;
}
__device__ __forceinline__ void cp_async16(uint32_t dst, const void* src) {
    asm volatile("cp.async.cg.shared.global [%0], [%1], 16;" :: "r"(dst), "l"(src));
}
#define CP_COMMIT() asm volatile("cp.async.commit_group;" ::: "memory")
#define CP_WAIT(n)  asm volatile("cp.async.wait_group %0;" :: "n"(n) : "memory")

__device__ __forceinline__ void ldsm4(uint32_t a, uint32_t* r) {
    asm volatile("ldmatrix.sync.aligned.m8n8.x4.shared.b16 {%0,%1,%2,%3}, [%4];"
        : "=r"(r[0]), "=r"(r[1]), "=r"(r[2]), "=r"(r[3]) : "r"(a));
}
__device__ __forceinline__ void ldsm4t(uint32_t a, uint32_t* r) {
    asm volatile("ldmatrix.sync.aligned.m8n8.x4.trans.shared.b16 {%0,%1,%2,%3}, [%4];"
        : "=r"(r[0]), "=r"(r[1]), "=r"(r[2]), "=r"(r[3]) : "r"(a));
}
__device__ __forceinline__ void mma_bf16(float* c, const uint32_t* a, const uint32_t* b) {
    asm volatile("mma.sync.aligned.m16n8k16.row.col.f32.bf16.bf16.f32 "
        "{%0,%1,%2,%3}, {%4,%5,%6,%7}, {%8,%9}, {%0,%1,%2,%3};"
        : "+f"(c[0]), "+f"(c[1]), "+f"(c[2]), "+f"(c[3])
        : "r"(a[0]), "r"(a[1]), "r"(a[2]), "r"(a[3]), "r"(b[0]), "r"(b[1]));
}
__device__ __forceinline__ void pack_hl(float p0, float p1, uint32_t& h, uint32_t& l) {
    __nv_bfloat162 hv = __floats2bfloat162_rn(p0, p1);
    __nv_bfloat162 lv = __floats2bfloat162_rn(p0 - __bfloat162float(hv.x),
                                              p1 - __bfloat162float(hv.y));
    h = *(uint32_t*)&hv;
    l = *(uint32_t*)&lv;
}

// ---------------------------------------------------------------------------
// fp32 -> bf16 hi/lo split. dstSel: 0 -> (g_ah,g_al), 1 -> (g_wh,g_wl)
// ---------------------------------------------------------------------------
__global__ void cvt_hilo_kernel(const float* __restrict__ src, int n4, int dstSel)
{
    __nv_bfloat16* hi = dstSel ? g_wh : g_ah;
    __nv_bfloat16* lo = dstSel ? g_wl : g_al;
    int i = blockIdx.x * blockDim.x + threadIdx.x;
    if (i >= n4) return;
    float4 v = ((const float4*)src)[i];
    __nv_bfloat162 h0 = __floats2bfloat162_rn(v.x, v.y);
    __nv_bfloat162 h1 = __floats2bfloat162_rn(v.z, v.w);
    __nv_bfloat162 l0 = __floats2bfloat162_rn(v.x - __bfloat162float(h0.x),
                                              v.y - __bfloat162float(h0.y));
    __nv_bfloat162 l1 = __floats2bfloat162_rn(v.z - __bfloat162float(h1.x),
                                              v.w - __bfloat162float(h1.y));
    ((__nv_bfloat162*)hi)[2*i]   = h0;
    ((__nv_bfloat162*)hi)[2*i+1] = h1;
    ((__nv_bfloat162*)lo)[2*i]   = l0;
    ((__nv_bfloat162*)lo)[2*i+1] = l1;
}

// ---------------------------------------------------------------------------
// GEMM: C = A @ W^T + bias via mma.sync bf16 (3-term hi/lo).
// 128x128 tile, K-chunk 32, double-buffered cp.async.
// 8 warps: warp tile 64(M) x 32(N).
// outSel 0/1/2 -> (g_qh,g_ql)/(g_kh,g_kl)/(g_vh,g_vl) head-split; 3 -> fp32 Cout.
// ---------------------------------------------------------------------------
#define GKC 32
#define GSTRIDE 80                 // 32 bf16 = 64B data + 16B pad
#define GBUF (128*GSTRIDE)         // 10240
#define GSTAGE (4*GBUF)            // Ah, Al, Wh, Wl
#define GEMM_SMEM (2*GSTAGE)       // 81920

__device__ __forceinline__ void g_load_stage(uint32_t sb, int stg, int bm, int bn,
                                             int k0, int tid)
{
    uint32_t base = sb + stg * GSTAGE;
#pragma unroll
    for (int j = 0; j < 8; j++) {
        int g = tid + 256 * j;
        int buf = g >> 9;            // 0:Ah 1:Al 2:Wh 3:Wl
        int cid = g & 511;
        int row = cid >> 2;
        int ch  = cid & 3;
        const __nv_bfloat16* src = (buf == 0) ? g_ah : (buf == 1) ? g_al
                                  : (buf == 2) ? g_wh : g_wl;
        int rbase = (buf < 2) ? bm : bn;
        const void* gp = src + (size_t)(rbase + row) * DMODEL + k0 + ch * 8;
        cp_async16(base + buf * GBUF + row * GSTRIDE + ch * 16, gp);
    }
}

__global__ __launch_bounds__(256, 1)
void gemm_mma_kernel(const float* __restrict__ bias, float* __restrict__ Cout, int outSel)
{
    extern __shared__ __align__(128) char smg[];
    const uint32_t sb = smem_u32(smg);
    const int tid = threadIdx.x;
    const int lane = tid & 31;
    const int wid = tid >> 5;
    const int wr = (wid >> 2) * 64;      // warp row base within tile
    const int wn = (wid & 3) * 32;       // warp col base within tile
    const int bm = blockIdx.y * 128;
    const int bn = blockIdx.x * 128;

    float acc[4][4][4];
#pragma unroll
    for (int a = 0; a < 4; a++)
#pragma unroll
        for (int b = 0; b < 4; b++)
#pragma unroll
            for (int c = 0; c < 4; c++) acc[a][b][c] = 0.f;

    g_load_stage(sb, 0, bm, bn, 0, tid);   CP_COMMIT();
    g_load_stage(sb, 1, bm, bn, GKC, tid); CP_COMMIT();

    const int NIT = DMODEL / GKC;   // 32
    // per-thread ldmatrix offsets
    const uint32_t a_row = (lane & 15);
    const uint32_t a_k8  = (lane >> 4) << 3;
    const uint32_t b_row = ((lane >> 4) << 3) + (lane & 7);
    const uint32_t b_k8  = ((lane >> 3) & 1) << 3;

    for (int it = 0; it < NIT; it++) {
        if (it == NIT - 1) { CP_WAIT(0); } else { CP_WAIT(1); }
        __syncthreads();
        uint32_t base = sb + (it & 1) * GSTAGE;

#pragma unroll
        for (int ks = 0; ks < 2; ks++) {
            const int k0 = ks * 16;
            uint32_t Ah[4][4], Al[4][4];
#pragma unroll
            for (int mf = 0; mf < 4; mf++) {
                uint32_t ra = base + (wr + mf * 16 + a_row) * GSTRIDE + (k0 + a_k8) * 2;
                ldsm4(ra, Ah[mf]);
                ldsm4(ra + GBUF, Al[mf]);
            }
#pragma unroll
            for (int np = 0; np < 2; np++) {
                uint32_t rb = base + 2 * GBUF + (wn + np * 16 + b_row) * GSTRIDE
                              + (k0 + b_k8) * 2;
                uint32_t Bh[4], Bl[4];
                ldsm4(rb, Bh);
                ldsm4(rb + GBUF, Bl);
#pragma unroll
                for (int mf = 0; mf < 4; mf++) {
#pragma unroll
                    for (int nn = 0; nn < 2; nn++) {
                        float* c = acc[mf][np * 2 + nn];
                        mma_bf16(c, Ah[mf], Bh + 2 * nn);
                        mma_bf16(c, Ah[mf], Bl + 2 * nn);
                        mma_bf16(c, Al[mf], Bh + 2 * nn);
                    }
                }
            }
        }
        __syncthreads();
        if (it + 2 < NIT) {
            g_load_stage(sb, it & 1, bm, bn, (it + 2) * GKC, tid);
            CP_COMMIT();
        }
    }

    // epilogue
    __nv_bfloat16* dsth = (outSel == 0) ? g_qh : (outSel == 1) ? g_kh : g_vh;
    __nv_bfloat16* dstl = (outSel == 0) ? g_ql : (outSel == 1) ? g_kl : g_vl;
#pragma unroll
    for (int mf = 0; mf < 4; mf++) {
#pragma unroll
        for (int nf = 0; nf < 4; nf++) {
            int r0 = bm + wr + mf * 16 + (lane >> 2);
            int c0 = bn + wn + nf * 8 + (lane & 3) * 2;
            float bs0 = bias[c0], bs1 = bias[c0 + 1];
#pragma unroll
            for (int hh = 0; hh < 2; hh++) {
                int row = r0 + 8 * hh;
                float v0 = acc[mf][nf][2 * hh + 0] + bs0;
                float v1 = acc[mf][nf][2 * hh + 1] + bs1;
                if (outSel < 3) {
                    int hd = c0 >> 6, d = c0 & 63;
                    int b = row >> 11, s = row & (SEQ - 1);
                    size_t idx = ((((size_t)b * NHEAD + hd) * SEQ) + s) * DK + d;
                    uint32_t hv, lv;
                    pack_hl(v0, v1, hv, lv);
                    *(uint32_t*)&dsth[idx] = hv;
                    *(uint32_t*)&dstl[idx] = lv;
                } else {
                    float2 o = make_float2(v0, v1);
                    *(float2*)&Cout[(size_t)row * DMODEL + c0] = o;
                }
            }
        }
    }
}

// ---------------------------------------------------------------------------
// Flash attention via mma.sync bf16 (3-term hi/lo for QK and PV).
// CTA: 128 q rows, 8 warps (16 rows each). KV streamed in 64-row tiles,
// double-buffered. P stays in registers (C-frag -> A-frag repack).
// Output written as bf16 hi/lo directly into g_ah/g_al ([B*S, DMODEL]).
// ---------------------------------------------------------------------------
#define ASTRIDE 144                  // 64 bf16 = 128B data + 16B pad
#define AQBUF (128*ASTRIDE)          // 18432
#define AKBUF (64*ASTRIDE)           // 9216
#define ASTAGE (4*AKBUF)             // Kh, Kl, Vh, Vl = 36864
#define ATT_SMEM (2*AQBUF + 2*ASTAGE)  // 110592

__device__ __forceinline__ void a_load_kv(uint32_t sb, int stg, int bh, int kt, int tid)
{
    uint32_t base = sb + 2 * AQBUF + stg * ASTAGE;
#pragma unroll
    for (int j = 0; j < 8; j++) {
        int g = tid + 256 * j;
        int buf = g >> 9;             // 0:Kh 1:Kl 2:Vh 3:Vl
        int cid = g & 511;
        int row = cid >> 3;
        int ch  = cid & 7;
        const __nv_bfloat16* src = (buf == 0) ? g_kh : (buf == 1) ? g_kl
                                  : (buf == 2) ? g_vh : g_vl;
        const void* gp = src + ((size_t)bh * SEQ + kt * 64 + row) * DK + ch * 8;
        cp_async16(base + buf * AKBUF + row * ASTRIDE + ch * 16, gp);
    }
}

__global__ __launch_bounds__(256, 1)
void attn_mma_kernel()
{
    extern __shared__ __align__(128) char sma[];
    const uint32_t sb = smem_u32(sma);
    const int tid = threadIdx.x;
    const int lane = tid & 31;
    const int wid = tid >> 5;
    const int bh = blockIdx.y;           // b*NHEAD + h
    const int q0 = blockIdx.x * 128;

    // load Q tile (hi/lo) via cp.async
#pragma unroll
    for (int j = 0; j < 8; j++) {
        int g = tid + 256 * j;
        int buf = g >> 10;           // 0:Qh 1:Ql
        int cid = g & 1023;
        int row = cid >> 3;
        int ch  = cid & 7;
        const __nv_bfloat16* src = buf ? g_ql : g_qh;
        const void* gp = src + ((size_t)bh * SEQ + q0 + row) * DK + ch * 8;
        cp_async16(sb + buf * AQBUF + row * ASTRIDE + ch * 16, gp);
    }
    CP_COMMIT();
    a_load_kv(sb, 0, bh, 0, tid); CP_COMMIT();
    a_load_kv(sb, 1, bh, 1, tid); CP_COMMIT();

    // Q fragments
    CP_WAIT(2);
    __syncthreads();
    const uint32_t a_row = (lane & 15);
    const uint32_t a_k8  = (lane >> 4) << 3;
    const uint32_t b_row = ((lane >> 4) << 3) + (lane & 7);
    const uint32_t b_k8  = ((lane >> 3) & 1) << 3;
    const uint32_t v_row = (((lane >> 3) & 1) << 3) + (lane & 7);
    const uint32_t v_c8  = (lane >> 4) << 3;

    uint32_t Qh[4][4], Ql[4][4];
    const int wq = wid * 16;
#pragma unroll
    for (int kf = 0; kf < 4; kf++) {
        uint32_t ra = sb + (wq + a_row) * ASTRIDE + (kf * 16 + a_k8) * 2;
        ldsm4(ra, Qh[kf]);
        ldsm4(ra + AQBUF, Ql[kf]);
    }

    float o[8][4];
#pragma unroll
    for (int i = 0; i < 8; i++)
#pragma unroll
        for (int k = 0; k < 4; k++) o[i][k] = 0.f;
    float m0 = -INFINITY, m1 = -INFINITY, l0 = 0.f, l1 = 0.f;

    const int NT = SEQ / 64;   // 32
    for (int it = 0; it < NT; it++) {
        if (it == NT - 1) { CP_WAIT(0); } else { CP_WAIT(1); }
        __syncthreads();
        uint32_t kb = sb + 2 * AQBUF + (it & 1) * ASTAGE;

        // ---- scores S = Q K^T ----
        float s[8][4];
#pragma unroll
        for (int i = 0; i < 8; i++)
#pragma unroll
            for (int k = 0; k < 4; k++) s[i][k] = 0.f;

#pragma unroll
        for (int ks = 0; ks < 4; ks++) {
#pragma unroll
            for (int np = 0; np < 4; np++) {
                uint32_t rb = kb + (np * 16 + b_row) * ASTRIDE + (ks * 16 + b_k8) * 2;
                uint32_t Bh[4], Bl[4];
                ldsm4(rb, Bh);
                ldsm4(rb + AKBUF, Bl);
#pragma unroll
                for (int nn = 0; nn < 2; nn++) {
                    float* c = s[np * 2 + nn];
                    mma_bf16(c, Qh[ks], Bh + 2 * nn);
                    mma_bf16(c, Qh[ks], Bl + 2 * nn);
                    mma_bf16(c, Ql[ks], Bh + 2 * nn);
                }
            }
        }

        // ---- online softmax ----
        float mx0 = -INFINITY, mx1 = -INFINITY;
#pragma unroll
        for (int i = 0; i < 8; i++) {
#pragma unroll
            for (int k = 0; k < 4; k++) s[i][k] *= 0.125f;
            mx0 = fmaxf(mx0, fmaxf(s[i][0], s[i][1]));
            mx1 = fmaxf(mx1, fmaxf(s[i][2], s[i][3]));
        }
        mx0 = fmaxf(mx0, __shfl_xor_sync(0xffffffffu, mx0, 1));
        mx0 = fmaxf(mx0, __shfl_xor_sync(0xffffffffu, mx0, 2));
        mx1 = fmaxf(mx1, __shfl_xor_sync(0xffffffffu, mx1, 1));
        mx1 = fmaxf(mx1, __shfl_xor_sync(0xffffffffu, mx1, 2));

        float mn0 = fmaxf(m0, mx0), mn1 = fmaxf(m1, mx1);
        float al0 = __expf(m0 - mn0), al1 = __expf(m1 - mn1);
        m0 = mn0; m1 = mn1;

        float rs0 = 0.f, rs1 = 0.f;
#pragma unroll
        for (int i = 0; i < 8; i++) {
            s[i][0] = __expf(s[i][0] - mn0);
            s[i][1] = __expf(s[i][1] - mn0);
            s[i][2] = __expf(s[i][2] - mn1);
            s[i][3] = __expf(s[i][3] - mn1);
            rs0 += s[i][0] + s[i][1];
            rs1 += s[i][2] + s[i][3];
        }
        rs0 += __shfl_xor_sync(0xffffffffu, rs0, 1);
        rs0 += __shfl_xor_sync(0xffffffffu, rs0, 2);
        rs1 += __shfl_xor_sync(0xffffffffu, rs1, 1);
        rs1 += __shfl_xor_sync(0xffffffffu, rs1, 2);
        l0 = l0 * al0 + rs0;
        l1 = l1 * al1 + rs1;
#pragma unroll
        for (int i = 0; i < 8; i++) {
            o[i][0] *= al0; o[i][1] *= al0;
            o[i][2] *= al1; o[i][3] *= al1;
        }

        // ---- repack P (C-frag -> A-frag, hi/lo) ----
        uint32_t Ph[4][4], Pl[4][4];
#pragma unroll
        for (int j = 0; j < 4; j++) {
            pack_hl(s[2*j][0],   s[2*j][1],   Ph[j][0], Pl[j][0]);
            pack_hl(s[2*j][2],   s[2*j][3],   Ph[j][1], Pl[j][1]);
            pack_hl(s[2*j+1][0], s[2*j+1][1], Ph[j][2], Pl[j][2]);
            pack_hl(s[2*j+1][2], s[2*j+1][3], Ph[j][3], Pl[j][3]);
        }

        // ---- O += P V ----
#pragma unroll
        for (int j = 0; j < 4; j++) {
#pragma unroll
            for (int np = 0; np < 4; np++) {
                uint32_t rv = kb + 2 * AKBUF + (j * 16 + v_row) * ASTRIDE
                              + (np * 16 + v_c8) * 2;
                uint32_t Vh[4], Vl[4];
                ldsm4t(rv, Vh);
                ldsm4t(rv + AKBUF, Vl);
#pragma unroll
                for (int nn = 0; nn < 2; nn++) {
                    float* c = o[np * 2 + nn];
                    mma_bf16(c, Ph[j], Vh + 2 * nn);
                    mma_bf16(c, Ph[j], Vl + 2 * nn);
                    mma_bf16(c, Pl[j], Vh + 2 * nn);
                }
            }
        }

        __syncthreads();
        if (it + 2 < NT) {
            a_load_kv(sb, it & 1, bh, it + 2, tid);
            CP_COMMIT();
        }
    }

    // ---- epilogue: write x as bf16 hi/lo into g_ah/g_al ----
    float inv0 = 1.0f / l0, inv1 = 1.0f / l1;
    const int b = bh >> 4;
    const int h = bh & (NHEAD - 1);
    const int qrow = q0 + wid * 16 + (lane >> 2);
#pragma unroll
    for (int nf = 0; nf < 8; nf++) {
        int d = h * DK + nf * 8 + (lane & 3) * 2;
        uint32_t hv, lv;
        size_t idx0 = ((size_t)b * SEQ + qrow) * DMODEL + d;
        pack_hl(o[nf][0] * inv0, o[nf][1] * inv0, hv, lv);
        *(uint32_t*)&g_ah[idx0] = hv;
        *(uint32_t*)&g_al[idx0] = lv;
        size_t idx1 = ((size_t)b * SEQ + qrow + 8) * DMODEL + d;
        pack_hl(o[nf][2] * inv1, o[nf][3] * inv1, hv, lv);
        *(uint32_t*)&g_ah[idx1] = hv;
        *(uint32_t*)&g_al[idx1] = lv;
    }
}

// ---------------------------------------------------------------------------
// Launch
// ---------------------------------------------------------------------------
extern "C" void kernel_launch(void* const* d_in, const int* in_sizes, int n_in,
                              void* d_out, int out_size)
{
    (void)in_sizes; (void)n_in; (void)out_size;
    const float* query = (const float*)d_in[0];
    const float* key   = (const float*)d_in[1];
    const float* value = (const float*)d_in[2];
    const float* Wq = (const float*)d_in[3];
    const float* bq = (const float*)d_in[4];
    const float* Wk = (const float*)d_in[5];
    const float* bk = (const float*)d_in[6];
    const float* Wv = (const float*)d_in[7];
    const float* bv = (const float*)d_in[8];
    const float* Wo = (const float*)d_in[9];
    const float* bo = (const float*)d_in[10];
    float* out = (float*)d_out;

    cudaFuncSetAttribute(gemm_mma_kernel, cudaFuncAttributeMaxDynamicSharedMemorySize,
                         GEMM_SMEM);
    cudaFuncSetAttribute(attn_mma_kernel, cudaFuncAttributeMaxDynamicSharedMemorySize,
                         ATT_SMEM);

    const int nA4 = MTOT * DMODEL / 4;
    const int nW4 = DMODEL * DMODEL / 4;
    dim3 ggrid(DMODEL / 128, MTOT / 128);   // (8, 64)

    cvt_hilo_kernel<<<nA4 / 256, 256>>>(query, nA4, 0);
    cvt_hilo_kernel<<<nW4 / 256, 256>>>(Wq, nW4, 1);
    gemm_mma_kernel<<<ggrid, 256, GEMM_SMEM>>>(bq, nullptr, 0);

    cvt_hilo_kernel<<<nA4 / 256, 256>>>(key, nA4, 0);
    cvt_hilo_kernel<<<nW4 / 256, 256>>>(Wk, nW4, 1);
    gemm_mma_kernel<<<ggrid, 256, GEMM_SMEM>>>(bk, nullptr, 1);

    cvt_hilo_kernel<<<nA4 / 256, 256>>>(value, nA4, 0);
    cvt_hilo_kernel<<<nW4 / 256, 256>>>(Wv, nW4, 1);
    gemm_mma_kernel<<<ggrid, 256, GEMM_SMEM>>>(bv, nullptr, 2);

    attn_mma_kernel<<<dim3(SEQ / 128, BATCH * NHEAD), 256, ATT_SMEM>>>();

    cvt_hilo_kernel<<<nW4 / 256, 256>>>(Wo, nW4, 1);
    gemm_mma_kernel<<<ggrid, 256, GEMM_SMEM>>>(bo, out, 3);
}

// round 4
// speedup vs baseline: 2.9686x; 1.0630x over previous
#include <cuda_runtime.h>
#include <cuda_bf16.h>
#include <math.h>
#include <stdint.h>

#define NHEAD 16
#define DK 64
#define DMODEL 1024
#define BATCH 4
#define SEQ 2048
#define MTOT (BATCH*SEQ)                  // 8192
#define ACTN ((size_t)MTOT*DMODEL)        // 8.39M elems
#define WN   ((size_t)DMODEL*DMODEL)      // 1.05M elems
#define HS   ((size_t)BATCH*NHEAD*SEQ*DK)

// ---------------- scratch ----------------
// act slots: 0=query/x, 1=key, 2=value ; weight slots: 0=Wq 1=Wk 2=Wv 3=Wo
__device__ __nv_bfloat16 g_ah[3*ACTN];
__device__ __nv_bfloat16 g_al[3*ACTN];
__device__ __nv_bfloat16 g_wh[4*WN];
__device__ __nv_bfloat16 g_wl[4*WN];
__device__ __nv_bfloat16 g_qh[HS], g_ql[HS];
__device__ __nv_bfloat16 g_kh[HS], g_kl[HS];
__device__ __nv_bfloat16 g_vh[HS], g_vl[HS];

// ---------------- helpers ----------------
__device__ __forceinline__ uint32_t smem_u32(const void* p) {
    uint32_t a;
    asm("{ .reg .u64 t; cvta.to.shared.u64 t, %1; cvt.u32.u64 %0, t; }" : "=r"(a) : "l"(p));
    return a;
}
__device__ __forceinline__ void cp_async16(uint32_t dst, const void* src) {
    asm volatile("cp.async.cg.shared.global [%0], [%1], 16;" :: "r"(dst), "l"(src));
}
#define CP_COMMIT() asm volatile("cp.async.commit_group;" ::: "memory")
#define CP_WAIT(n)  asm volatile("cp.async.wait_group %0;" :: "n"(n) : "memory")

__device__ __forceinline__ void ldsm4(uint32_t a, uint32_t* r) {
    asm volatile("ldmatrix.sync.aligned.m8n8.x4.shared.b16 {%0,%1,%2,%3}, [%4];"
        : "=r"(r[0]), "=r"(r[1]), "=r"(r[2]), "=r"(r[3]) : "r"(a));
}
__device__ __forceinline__ void ldsm4t(uint32_t a, uint32_t* r) {
    asm volatile("ldmatrix.sync.aligned.m8n8.x4.trans.shared.b16 {%0,%1,%2,%3}, [%4];"
        : "=r"(r[0]), "=r"(r[1]), "=r"(r[2]), "=r"(r[3]) : "r"(a));
}
__device__ __forceinline__ void mma_bf16(float* c, const uint32_t* a, const uint32_t* b) {
    asm volatile("mma.sync.aligned.m16n8k16.row.col.f32.bf16.bf16.f32 "
        "{%0,%1,%2,%3}, {%4,%5,%6,%7}, {%8,%9}, {%0,%1,%2,%3};"
        : "+f"(c[0]), "+f"(c[1]), "+f"(c[2]), "+f"(c[3])
        : "r"(a[0]), "r"(a[1]), "r"(a[2]), "r"(a[3]), "r"(b[0]), "r"(b[1]));
}
__device__ __forceinline__ void pack_hl(float p0, float p1, uint32_t& h, uint32_t& l) {
    __nv_bfloat162 hv = __floats2bfloat162_rn(p0, p1);
    __nv_bfloat162 lv = __floats2bfloat162_rn(p0 - __bfloat162float(hv.x),
                                              p1 - __bfloat162float(hv.y));
    h = *(uint32_t*)&hv;
    l = *(uint32_t*)&lv;
}

// ---------------------------------------------------------------------------
// fp32 -> bf16 hi/lo converts (merged: acts via blockIdx.y, weights via blockIdx.y)
// ---------------------------------------------------------------------------
__global__ void cvt_act_kernel(const float* __restrict__ q, const float* __restrict__ k,
                               const float* __restrict__ v, int n4)
{
    int z = blockIdx.y;
    const float* src = (z == 0) ? q : (z == 1) ? k : v;
    __nv_bfloat16* hi = g_ah + (size_t)z * ACTN;
    __nv_bfloat16* lo = g_al + (size_t)z * ACTN;
    int i = blockIdx.x * blockDim.x + threadIdx.x;
    if (i >= n4) return;
    float4 vv = ((const float4*)src)[i];
    __nv_bfloat162 h0 = __floats2bfloat162_rn(vv.x, vv.y);
    __nv_bfloat162 h1 = __floats2bfloat162_rn(vv.z, vv.w);
    __nv_bfloat162 l0 = __floats2bfloat162_rn(vv.x - __bfloat162float(h0.x),
                                              vv.y - __bfloat162float(h0.y));
    __nv_bfloat162 l1 = __floats2bfloat162_rn(vv.z - __bfloat162float(h1.x),
                                              vv.w - __bfloat162float(h1.y));
    ((__nv_bfloat162*)hi)[2*i]   = h0;
    ((__nv_bfloat162*)hi)[2*i+1] = h1;
    ((__nv_bfloat162*)lo)[2*i]   = l0;
    ((__nv_bfloat162*)lo)[2*i+1] = l1;
}

__global__ void cvt_w_kernel(const float* __restrict__ w0, const float* __restrict__ w1,
                             const float* __restrict__ w2, const float* __restrict__ w3,
                             int n4)
{
    int z = blockIdx.y;
    const float* src = (z == 0) ? w0 : (z == 1) ? w1 : (z == 2) ? w2 : w3;
    __nv_bfloat16* hi = g_wh + (size_t)z * WN;
    __nv_bfloat16* lo = g_wl + (size_t)z * WN;
    int i = blockIdx.x * blockDim.x + threadIdx.x;
    if (i >= n4) return;
    float4 vv = ((const float4*)src)[i];
    __nv_bfloat162 h0 = __floats2bfloat162_rn(vv.x, vv.y);
    __nv_bfloat162 h1 = __floats2bfloat162_rn(vv.z, vv.w);
    __nv_bfloat162 l0 = __floats2bfloat162_rn(vv.x - __bfloat162float(h0.x),
                                              vv.y - __bfloat162float(h0.y));
    __nv_bfloat162 l1 = __floats2bfloat162_rn(vv.z - __bfloat162float(h1.x),
                                              vv.w - __bfloat162float(h1.y));
    ((__nv_bfloat162*)hi)[2*i]   = h0;
    ((__nv_bfloat162*)hi)[2*i+1] = h1;
    ((__nv_bfloat162*)lo)[2*i]   = l0;
    ((__nv_bfloat162*)lo)[2*i+1] = l1;
}

// ---------------------------------------------------------------------------
// GEMM: C = A @ W^T + bias via mma.sync bf16 (3-term hi/lo).
// 128x128 tile, K-chunk 32, 4-stage cp.async pipeline, one barrier/iter.
// mode 0: fused QKV (blockIdx.z selects act slot, W slot, bias, dest hi/lo).
// mode 1: final projection (act slot 0, W slot 3, fp32 out).
// ---------------------------------------------------------------------------
#define GKC 32
#define GSTRIDE 80                 // 32 bf16 = 64B data + 16B pad
#define GBUF (128*GSTRIDE)         // 10240
#define GSTAGE (4*GBUF)            // Ah, Al, Wh, Wl = 40960
#define GNSTG 4
#define GEMM_SMEM (GNSTG*GSTAGE)   // 163840

__device__ __forceinline__ void g_load_stage(uint32_t sb, int stg,
                                             const __nv_bfloat16* Ah_g,
                                             const __nv_bfloat16* Al_g,
                                             const __nv_bfloat16* Wh_g,
                                             const __nv_bfloat16* Wl_g,
                                             int bm, int bn, int k0, int tid)
{
    uint32_t base = sb + stg * GSTAGE;
#pragma unroll
    for (int j = 0; j < 8; j++) {
        int g = tid + 256 * j;
        int buf = g >> 9;            // 0:Ah 1:Al 2:Wh 3:Wl
        int cid = g & 511;
        int row = cid >> 2;
        int ch  = cid & 3;
        const __nv_bfloat16* src = (buf == 0) ? Ah_g : (buf == 1) ? Al_g
                                  : (buf == 2) ? Wh_g : Wl_g;
        int rbase = (buf < 2) ? bm : bn;
        const void* gp = src + (size_t)(rbase + row) * DMODEL + k0 + ch * 8;
        cp_async16(base + buf * GBUF + row * GSTRIDE + ch * 16, gp);
    }
}

__global__ __launch_bounds__(256, 1)
void gemm_mma_kernel(const float* __restrict__ b0, const float* __restrict__ b1,
                     const float* __restrict__ b2, float* __restrict__ Cout, int mode)
{
    extern __shared__ __align__(128) char smg[];
    const uint32_t sb = smem_u32(smg);
    const int tid = threadIdx.x;
    const int lane = tid & 31;
    const int wid = tid >> 5;
    const int wr = (wid >> 2) * 64;
    const int wn = (wid & 3) * 32;
    const int bm = blockIdx.y * 128;
    const int bn = blockIdx.x * 128;
    const int z = blockIdx.z;

    const int aslot = (mode == 0) ? z : 0;
    const int wslot = (mode == 0) ? z : 3;
    const __nv_bfloat16* Ah_g = g_ah + (size_t)aslot * ACTN;
    const __nv_bfloat16* Al_g = g_al + (size_t)aslot * ACTN;
    const __nv_bfloat16* Wh_g = g_wh + (size_t)wslot * WN;
    const __nv_bfloat16* Wl_g = g_wl + (size_t)wslot * WN;
    const float* bias = (mode == 1) ? b0 : (z == 0) ? b0 : (z == 1) ? b1 : b2;

    float acc[4][4][4];
#pragma unroll
    for (int a = 0; a < 4; a++)
#pragma unroll
        for (int b = 0; b < 4; b++)
#pragma unroll
            for (int c = 0; c < 4; c++) acc[a][b][c] = 0.f;

    g_load_stage(sb, 0, Ah_g, Al_g, Wh_g, Wl_g, bm, bn, 0, tid);       CP_COMMIT();
    g_load_stage(sb, 1, Ah_g, Al_g, Wh_g, Wl_g, bm, bn, GKC, tid);     CP_COMMIT();
    g_load_stage(sb, 2, Ah_g, Al_g, Wh_g, Wl_g, bm, bn, 2 * GKC, tid); CP_COMMIT();

    const int NIT = DMODEL / GKC;   // 32
    const uint32_t a_row = (lane & 15);
    const uint32_t a_k8  = (lane >> 4) << 3;
    const uint32_t b_row = ((lane >> 4) << 3) + (lane & 7);
    const uint32_t b_k8  = ((lane >> 3) & 1) << 3;

    for (int it = 0; it < NIT; it++) {
        int rem = NIT - 1 - it;
        if      (rem >= 2) { CP_WAIT(2); }
        else if (rem == 1) { CP_WAIT(1); }
        else               { CP_WAIT(0); }
        __syncthreads();

        if (it + 3 < NIT) {
            g_load_stage(sb, (it + 3) & 3, Ah_g, Al_g, Wh_g, Wl_g,
                         bm, bn, (it + 3) * GKC, tid);
            CP_COMMIT();
        }

        uint32_t base = sb + (it & 3) * GSTAGE;
#pragma unroll
        for (int ks = 0; ks < 2; ks++) {
            const int k0 = ks * 16;
            uint32_t Ah[4][4], Al[4][4], Bh[2][4], Bl[2][4];
#pragma unroll
            for (int mf = 0; mf < 4; mf++) {
                uint32_t ra = base + (wr + mf * 16 + a_row) * GSTRIDE + (k0 + a_k8) * 2;
                ldsm4(ra, Ah[mf]);
                ldsm4(ra + GBUF, Al[mf]);
            }
#pragma unroll
            for (int np = 0; np < 2; np++) {
                uint32_t rb = base + 2 * GBUF + (wn + np * 16 + b_row) * GSTRIDE
                              + (k0 + b_k8) * 2;
                ldsm4(rb, Bh[np]);
                ldsm4(rb + GBUF, Bl[np]);
            }
            // term-major: hh, hl, lh (same-acc MMAs spaced 16 apart)
#pragma unroll
            for (int np = 0; np < 2; np++)
#pragma unroll
                for (int nn = 0; nn < 2; nn++)
#pragma unroll
                    for (int mf = 0; mf < 4; mf++)
                        mma_bf16(acc[mf][np * 2 + nn], Ah[mf], Bh[np] + 2 * nn);
#pragma unroll
            for (int np = 0; np < 2; np++)
#pragma unroll
                for (int nn = 0; nn < 2; nn++)
#pragma unroll
                    for (int mf = 0; mf < 4; mf++)
                        mma_bf16(acc[mf][np * 2 + nn], Ah[mf], Bl[np] + 2 * nn);
#pragma unroll
            for (int np = 0; np < 2; np++)
#pragma unroll
                for (int nn = 0; nn < 2; nn++)
#pragma unroll
                    for (int mf = 0; mf < 4; mf++)
                        mma_bf16(acc[mf][np * 2 + nn], Al[mf], Bh[np] + 2 * nn);
        }
    }

    // epilogue
    __nv_bfloat16* dsth = (z == 0) ? g_qh : (z == 1) ? g_kh : g_vh;
    __nv_bfloat16* dstl = (z == 0) ? g_ql : (z == 1) ? g_kl : g_vl;
#pragma unroll
    for (int mf = 0; mf < 4; mf++) {
#pragma unroll
        for (int nf = 0; nf < 4; nf++) {
            int r0 = bm + wr + mf * 16 + (lane >> 2);
            int c0 = bn + wn + nf * 8 + (lane & 3) * 2;
            float bs0 = bias[c0], bs1 = bias[c0 + 1];
#pragma unroll
            for (int hh = 0; hh < 2; hh++) {
                int row = r0 + 8 * hh;
                float v0 = acc[mf][nf][2 * hh + 0] + bs0;
                float v1 = acc[mf][nf][2 * hh + 1] + bs1;
                if (mode == 0) {
                    int hd = c0 >> 6, d = c0 & 63;
                    int b = row >> 11, s = row & (SEQ - 1);
                    size_t idx = ((((size_t)b * NHEAD + hd) * SEQ) + s) * DK + d;
                    uint32_t hv, lv;
                    pack_hl(v0, v1, hv, lv);
                    *(uint32_t*)&dsth[idx] = hv;
                    *(uint32_t*)&dstl[idx] = lv;
                } else {
                    float2 o = make_float2(v0, v1);
                    *(float2*)&Cout[(size_t)row * DMODEL + c0] = o;
                }
            }
        }
    }
}

// ---------------------------------------------------------------------------
// Flash attention via mma.sync bf16 (3-term hi/lo), 4-stage KV pipeline,
// one barrier per KV tile. Output written bf16 hi/lo into act slot 0.
// ---------------------------------------------------------------------------
#define ASTRIDE 144                  // 64 bf16 = 128B data + 16B pad
#define AQBUF (128*ASTRIDE)          // 18432
#define AKBUF (64*ASTRIDE)           // 9216
#define ASTAGE (4*AKBUF)             // Kh, Kl, Vh, Vl = 36864
#define ANSTG 4
#define ATT_SMEM (2*AQBUF + ANSTG*ASTAGE)   // 184320

__device__ __forceinline__ void a_load_kv(uint32_t sb, int stg, int bh, int kt, int tid)
{
    uint32_t base = sb + 2 * AQBUF + stg * ASTAGE;
#pragma unroll
    for (int j = 0; j < 8; j++) {
        int g = tid + 256 * j;
        int buf = g >> 9;             // 0:Kh 1:Kl 2:Vh 3:Vl
        int cid = g & 511;
        int row = cid >> 3;
        int ch  = cid & 7;
        const __nv_bfloat16* src = (buf == 0) ? g_kh : (buf == 1) ? g_kl
                                  : (buf == 2) ? g_vh : g_vl;
        const void* gp = src + ((size_t)bh * SEQ + kt * 64 + row) * DK + ch * 8;
        cp_async16(base + buf * AKBUF + row * ASTRIDE + ch * 16, gp);
    }
}

__global__ __launch_bounds__(256, 1)
void attn_mma_kernel()
{
    extern __shared__ __align__(128) char sma[];
    const uint32_t sb = smem_u32(sma);
    const int tid = threadIdx.x;
    const int lane = tid & 31;
    const int wid = tid >> 5;
    const int bh = blockIdx.y;           // b*NHEAD + h
    const int q0 = blockIdx.x * 128;

    // Q tile (hi/lo)
#pragma unroll
    for (int j = 0; j < 8; j++) {
        int g = tid + 256 * j;
        int buf = g >> 10;           // 0:Qh 1:Ql
        int cid = g & 1023;
        int row = cid >> 3;
        int ch  = cid & 7;
        const __nv_bfloat16* src = buf ? g_ql : g_qh;
        const void* gp = src + ((size_t)bh * SEQ + q0 + row) * DK + ch * 8;
        cp_async16(sb + buf * AQBUF + row * ASTRIDE + ch * 16, gp);
    }
    CP_COMMIT();
    a_load_kv(sb, 0, bh, 0, tid); CP_COMMIT();
    a_load_kv(sb, 1, bh, 1, tid); CP_COMMIT();
    a_load_kv(sb, 2, bh, 2, tid); CP_COMMIT();

    CP_WAIT(3);
    __syncthreads();
    const uint32_t a_row = (lane & 15);
    const uint32_t a_k8  = (lane >> 4) << 3;
    const uint32_t b_row = ((lane >> 4) << 3) + (lane & 7);
    const uint32_t b_k8  = ((lane >> 3) & 1) << 3;
    const uint32_t v_row = (((lane >> 3) & 1) << 3) + (lane & 7);
    const uint32_t v_c8  = (lane >> 4) << 3;

    uint32_t Qh[4][4], Ql[4][4];
    const int wq = wid * 16;
#pragma unroll
    for (int kf = 0; kf < 4; kf++) {
        uint32_t ra = sb + (wq + a_row) * ASTRIDE + (kf * 16 + a_k8) * 2;
        ldsm4(ra, Qh[kf]);
        ldsm4(ra + AQBUF, Ql[kf]);
    }

    float o[8][4];
#pragma unroll
    for (int i = 0; i < 8; i++)
#pragma unroll
        for (int k = 0; k < 4; k++) o[i][k] = 0.f;
    float m0 = -INFINITY, m1 = -INFINITY, l0 = 0.f, l1 = 0.f;

    const int NT = SEQ / 64;   // 32
    for (int it = 0; it < NT; it++) {
        int rem = NT - 1 - it;
        if      (rem >= 2) { CP_WAIT(2); }
        else if (rem == 1) { CP_WAIT(1); }
        else               { CP_WAIT(0); }
        __syncthreads();

        if (it + 3 < NT) {
            a_load_kv(sb, (it + 3) & 3, bh, it + 3, tid);
            CP_COMMIT();
        }

        uint32_t kb = sb + 2 * AQBUF + (it & 3) * ASTAGE;

        // ---- S = Q K^T ----
        float s[8][4];
#pragma unroll
        for (int i = 0; i < 8; i++)
#pragma unroll
            for (int k = 0; k < 4; k++) s[i][k] = 0.f;

#pragma unroll
        for (int ks = 0; ks < 4; ks++) {
#pragma unroll
            for (int np = 0; np < 4; np++) {
                uint32_t rb = kb + (np * 16 + b_row) * ASTRIDE + (ks * 16 + b_k8) * 2;
                uint32_t Bh[4], Bl[4];
                ldsm4(rb, Bh);
                ldsm4(rb + AKBUF, Bl);
#pragma unroll
                for (int nn = 0; nn < 2; nn++)
                    mma_bf16(s[np * 2 + nn], Qh[ks], Bh + 2 * nn);
#pragma unroll
                for (int nn = 0; nn < 2; nn++)
                    mma_bf16(s[np * 2 + nn], Qh[ks], Bl + 2 * nn);
#pragma unroll
                for (int nn = 0; nn < 2; nn++)
                    mma_bf16(s[np * 2 + nn], Ql[ks], Bh + 2 * nn);
            }
        }

        // ---- online softmax ----
        float mx0 = -INFINITY, mx1 = -INFINITY;
#pragma unroll
        for (int i = 0; i < 8; i++) {
#pragma unroll
            for (int k = 0; k < 4; k++) s[i][k] *= 0.125f;
            mx0 = fmaxf(mx0, fmaxf(s[i][0], s[i][1]));
            mx1 = fmaxf(mx1, fmaxf(s[i][2], s[i][3]));
        }
        mx0 = fmaxf(mx0, __shfl_xor_sync(0xffffffffu, mx0, 1));
        mx0 = fmaxf(mx0, __shfl_xor_sync(0xffffffffu, mx0, 2));
        mx1 = fmaxf(mx1, __shfl_xor_sync(0xffffffffu, mx1, 1));
        mx1 = fmaxf(mx1, __shfl_xor_sync(0xffffffffu, mx1, 2));

        float mn0 = fmaxf(m0, mx0), mn1 = fmaxf(m1, mx1);
        float al0 = __expf(m0 - mn0), al1 = __expf(m1 - mn1);
        m0 = mn0; m1 = mn1;

        float rs0 = 0.f, rs1 = 0.f;
#pragma unroll
        for (int i = 0; i < 8; i++) {
            s[i][0] = __expf(s[i][0] - mn0);
            s[i][1] = __expf(s[i][1] - mn0);
            s[i][2] = __expf(s[i][2] - mn1);
            s[i][3] = __expf(s[i][3] - mn1);
            rs0 += s[i][0] + s[i][1];
            rs1 += s[i][2] + s[i][3];
        }
        rs0 += __shfl_xor_sync(0xffffffffu, rs0, 1);
        rs0 += __shfl_xor_sync(0xffffffffu, rs0, 2);
        rs1 += __shfl_xor_sync(0xffffffffu, rs1, 1);
        rs1 += __shfl_xor_sync(0xffffffffu, rs1, 2);
        l0 = l0 * al0 + rs0;
        l1 = l1 * al1 + rs1;
#pragma unroll
        for (int i = 0; i < 8; i++) {
            o[i][0] *= al0; o[i][1] *= al0;
            o[i][2] *= al1; o[i][3] *= al1;
        }

        // ---- repack P -> A-frags (hi/lo) ----
        uint32_t Ph[4][4], Pl[4][4];
#pragma unroll
        for (int j = 0; j < 4; j++) {
            pack_hl(s[2*j][0],   s[2*j][1],   Ph[j][0], Pl[j][0]);
            pack_hl(s[2*j][2],   s[2*j][3],   Ph[j][1], Pl[j][1]);
            pack_hl(s[2*j+1][0], s[2*j+1][1], Ph[j][2], Pl[j][2]);
            pack_hl(s[2*j+1][2], s[2*j+1][3], Ph[j][3], Pl[j][3]);
        }

        // ---- O += P V ----
#pragma unroll
        for (int j = 0; j < 4; j++) {
#pragma unroll
            for (int np = 0; np < 4; np++) {
                uint32_t rv = kb + 2 * AKBUF + (j * 16 + v_row) * ASTRIDE
                              + (np * 16 + v_c8) * 2;
                uint32_t Vh[4], Vl[4];
                ldsm4t(rv, Vh);
                ldsm4t(rv + AKBUF, Vl);
#pragma unroll
                for (int nn = 0; nn < 2; nn++)
                    mma_bf16(o[np * 2 + nn], Ph[j], Vh + 2 * nn);
#pragma unroll
                for (int nn = 0; nn < 2; nn++)
                    mma_bf16(o[np * 2 + nn], Ph[j], Vl + 2 * nn);
#pragma unroll
                for (int nn = 0; nn < 2; nn++)
                    mma_bf16(o[np * 2 + nn], Pl[j], Vh + 2 * nn);
            }
        }
    }

    // ---- epilogue: write x hi/lo into act slot 0 ----
    float inv0 = 1.0f / l0, inv1 = 1.0f / l1;
    const int b = bh >> 4;
    const int h = bh & (NHEAD - 1);
    const int qrow = q0 + wid * 16 + (lane >> 2);
#pragma unroll
    for (int nf = 0; nf < 8; nf++) {
        int d = h * DK + nf * 8 + (lane & 3) * 2;
        uint32_t hv, lv;
        size_t idx0 = ((size_t)b * SEQ + qrow) * DMODEL + d;
        pack_hl(o[nf][0] * inv0, o[nf][1] * inv0, hv, lv);
        *(uint32_t*)&g_ah[idx0] = hv;
        *(uint32_t*)&g_al[idx0] = lv;
        size_t idx1 = ((size_t)b * SEQ + qrow + 8) * DMODEL + d;
        pack_hl(o[nf][2] * inv1, o[nf][3] * inv1, hv, lv);
        *(uint32_t*)&g_ah[idx1] = hv;
        *(uint32_t*)&g_al[idx1] = lv;
    }
}

// ---------------------------------------------------------------------------
// Launch: 5 kernels total.
// ---------------------------------------------------------------------------
extern "C" void kernel_launch(void* const* d_in, const int* in_sizes, int n_in,
                              void* d_out, int out_size)
{
    (void)in_sizes; (void)n_in; (void)out_size;
    const float* query = (const float*)d_in[0];
    const float* key   = (const float*)d_in[1];
    const float* value = (const float*)d_in[2];
    const float* Wq = (const float*)d_in[3];
    const float* bq = (const float*)d_in[4];
    const float* Wk = (const float*)d_in[5];
    const float* bk = (const float*)d_in[6];
    const float* Wv = (const float*)d_in[7];
    const float* bv = (const float*)d_in[8];
    const float* Wo = (const float*)d_in[9];
    const float* bo = (const float*)d_in[10];
    float* out = (float*)d_out;

    cudaFuncSetAttribute(gemm_mma_kernel, cudaFuncAttributeMaxDynamicSharedMemorySize,
                         GEMM_SMEM);
    cudaFuncSetAttribute(attn_mma_kernel, cudaFuncAttributeMaxDynamicSharedMemorySize,
                         ATT_SMEM);

    const int nA4 = (int)(ACTN / 4);
    const int nW4 = (int)(WN / 4);

    cvt_w_kernel<<<dim3(nW4 / 256, 4), 256>>>(Wq, Wk, Wv, Wo, nW4);
    cvt_act_kernel<<<dim3(nA4 / 256, 3), 256>>>(query, key, value, nA4);

    gemm_mma_kernel<<<dim3(8, 64, 3), 256, GEMM_SMEM>>>(bq, bk, bv, nullptr, 0);

    attn_mma_kernel<<<dim3(SEQ / 128, BATCH * NHEAD), 256, ATT_SMEM>>>();

    gemm_mma_kernel<<<dim3(8, 64, 1), 256, GEMM_SMEM>>>(bo, bo, bo, out, 1);
}

// round 6
// speedup vs baseline: 3.0948x; 1.0425x over previous
#include <cuda_runtime.h>
#include <cuda_bf16.h>
#include <math.h>
#include <stdint.h>

#define NHEAD 16
#define DK 64
#define DMODEL 1024
#define BATCH 4
#define SEQ 2048
#define MTOT (BATCH*SEQ)                  // 8192
#define ACTN ((size_t)MTOT*DMODEL)
#define WN   ((size_t)DMODEL*DMODEL)
#define HS   ((size_t)BATCH*NHEAD*SEQ*DK)

// act slots: 0=query/x, 1=key, 2=value ; weight slots: 0=Wq 1=Wk 2=Wv 3=Wo
__device__ __nv_bfloat16 g_ah[3*ACTN];
__device__ __nv_bfloat16 g_al[3*ACTN];
__device__ __nv_bfloat16 g_wh[4*WN];
__device__ __nv_bfloat16 g_wl[4*WN];
__device__ __nv_bfloat16 g_qh[HS], g_ql[HS];
__device__ __nv_bfloat16 g_kh[HS], g_kl[HS];
__device__ __nv_bfloat16 g_vh[HS], g_vl[HS];

// ---------------- helpers ----------------
__device__ __forceinline__ uint32_t smem_u32(const void* p) {
    uint32_t a;
    asm("{ .reg .u64 t; cvta.to.shared.u64 t, %1; cvt.u32.u64 %0, t; }" : "=r"(a) : "l"(p));
    return a;
}
__device__ __forceinline__ void cp_async16(uint32_t dst, const void* src) {
    asm volatile("cp.async.cg.shared.global [%0], [%1], 16;" :: "r"(dst), "l"(src));
}
#define CP_COMMIT() asm volatile("cp.async.commit_group;" ::: "memory")
#define CP_WAIT(n)  asm volatile("cp.async.wait_group %0;" :: "n"(n) : "memory")

__device__ __forceinline__ void ldsm4(uint32_t a, uint32_t* r) {
    asm volatile("ldmatrix.sync.aligned.m8n8.x4.shared.b16 {%0,%1,%2,%3}, [%4];"
        : "=r"(r[0]), "=r"(r[1]), "=r"(r[2]), "=r"(r[3]) : "r"(a));
}
__device__ __forceinline__ void ldsm4t(uint32_t a, uint32_t* r) {
    asm volatile("ldmatrix.sync.aligned.m8n8.x4.trans.shared.b16 {%0,%1,%2,%3}, [%4];"
        : "=r"(r[0]), "=r"(r[1]), "=r"(r[2]), "=r"(r[3]) : "r"(a));
}
__device__ __forceinline__ void mma_bf16(float* c, const uint32_t* a, const uint32_t* b) {
    asm volatile("mma.sync.aligned.m16n8k16.row.col.f32.bf16.bf16.f32 "
        "{%0,%1,%2,%3}, {%4,%5,%6,%7}, {%8,%9}, {%0,%1,%2,%3};"
        : "+f"(c[0]), "+f"(c[1]), "+f"(c[2]), "+f"(c[3])
        : "r"(a[0]), "r"(a[1]), "r"(a[2]), "r"(a[3]), "r"(b[0]), "r"(b[1]));
}
__device__ __forceinline__ void pack_hl(float p0, float p1, uint32_t& h, uint32_t& l) {
    __nv_bfloat162 hv = __floats2bfloat162_rn(p0, p1);
    __nv_bfloat162 lv = __floats2bfloat162_rn(p0 - __bfloat162float(hv.x),
                                              p1 - __bfloat162float(hv.y));
    h = *(uint32_t*)&hv;
    l = *(uint32_t*)&lv;
}

// ---------------------------------------------------------------------------
// fp32 -> bf16 hi/lo converts
// ---------------------------------------------------------------------------
__global__ void cvt_act_kernel(const float* __restrict__ q, const float* __restrict__ k,
                               const float* __restrict__ v, int n4)
{
    int z = blockIdx.y;
    const float* src = (z == 0) ? q : (z == 1) ? k : v;
    __nv_bfloat16* hi = g_ah + (size_t)z * ACTN;
    __nv_bfloat16* lo = g_al + (size_t)z * ACTN;
    int i = blockIdx.x * blockDim.x + threadIdx.x;
    if (i >= n4) return;
    float4 vv = ((const float4*)src)[i];
    __nv_bfloat162 h0 = __floats2bfloat162_rn(vv.x, vv.y);
    __nv_bfloat162 h1 = __floats2bfloat162_rn(vv.z, vv.w);
    __nv_bfloat162 l0 = __floats2bfloat162_rn(vv.x - __bfloat162float(h0.x),
                                              vv.y - __bfloat162float(h0.y));
    __nv_bfloat162 l1 = __floats2bfloat162_rn(vv.z - __bfloat162float(h1.x),
                                              vv.w - __bfloat162float(h1.y));
    ((__nv_bfloat162*)hi)[2*i]   = h0;
    ((__nv_bfloat162*)hi)[2*i+1] = h1;
    ((__nv_bfloat162*)lo)[2*i]   = l0;
    ((__nv_bfloat162*)lo)[2*i+1] = l1;
}

__global__ void cvt_w_kernel(const float* __restrict__ w0, const float* __restrict__ w1,
                             const float* __restrict__ w2, const float* __restrict__ w3,
                             int n4)
{
    int z = blockIdx.y;
    const float* src = (z == 0) ? w0 : (z == 1) ? w1 : (z == 2) ? w2 : w3;
    __nv_bfloat16* hi = g_wh + (size_t)z * WN;
    __nv_bfloat16* lo = g_wl + (size_t)z * WN;
    int i = blockIdx.x * blockDim.x + threadIdx.x;
    if (i >= n4) return;
    float4 vv = ((const float4*)src)[i];
    __nv_bfloat162 h0 = __floats2bfloat162_rn(vv.x, vv.y);
    __nv_bfloat162 h1 = __floats2bfloat162_rn(vv.z, vv.w);
    __nv_bfloat162 l0 = __floats2bfloat162_rn(vv.x - __bfloat162float(h0.x),
                                              vv.y - __bfloat162float(h0.y));
    __nv_bfloat162 l1 = __floats2bfloat162_rn(vv.z - __bfloat162float(h1.x),
                                              vv.w - __bfloat162float(h1.y));
    ((__nv_bfloat162*)hi)[2*i]   = h0;
    ((__nv_bfloat162*)hi)[2*i+1] = h1;
    ((__nv_bfloat162*)lo)[2*i]   = l0;
    ((__nv_bfloat162*)lo)[2*i+1] = l1;
}

// ---------------------------------------------------------------------------
// GEMM: C = A @ W^T + bias, 3-term hi/lo mma.sync.
// CTA tile 128(M) x 64(N), K-chunk 32, 3-stage pipeline, 2 CTAs/SM.
// 8 warps as 4(M) x 2(N); warp tile 32x32, acc 32 regs/thread.
// mode 0: fused QKV (z picks slot; z==0 output scaled by 0.125).
// mode 1: final projection (act 0, W 3, fp32 out).
// ---------------------------------------------------------------------------
#define GKC 32
#define GSTRIDE 80                 // 32 bf16 = 64B + 16B pad
#define GA_BUF (128*GSTRIDE)       // 10240
#define GW_BUF (64*GSTRIDE)        // 5120
#define GWOFF (2*GA_BUF)           // 20480
#define GASTAGE (2*GA_BUF + 2*GW_BUF)   // 30720
#define GNSTG 3
#define GEMM_SMEM (GNSTG*GASTAGE)  // 92160

__device__ __forceinline__ void g_load_stage(uint32_t sb, int stg,
                                             const __nv_bfloat16* Ah_g,
                                             const __nv_bfloat16* Al_g,
                                             const __nv_bfloat16* Wh_g,
                                             const __nv_bfloat16* Wl_g,
                                             int bm, int bn, int k0, int tid)
{
    uint32_t base = sb + stg * GASTAGE;
#pragma unroll
    for (int j = 0; j < 6; j++) {
        int g = tid + 256 * j;            // 0..1535
        if (g < 1024) {
            int buf = g >> 9;             // 0:Ah 1:Al
            int cid = g & 511;
            int row = cid >> 2;
            int ch  = cid & 3;
            const __nv_bfloat16* src = buf ? Al_g : Ah_g;
            cp_async16(base + buf * GA_BUF + row * GSTRIDE + ch * 16,
                       src + (size_t)(bm + row) * DMODEL + k0 + ch * 8);
        } else {
            int h = g - 1024;
            int buf = h >> 8;             // 0:Wh 1:Wl
            int cid = h & 255;
            int row = cid >> 2;
            int ch  = cid & 3;
            const __nv_bfloat16* src = buf ? Wl_g : Wh_g;
            cp_async16(base + GWOFF + buf * GW_BUF + row * GSTRIDE + ch * 16,
                       src + (size_t)(bn + row) * DMODEL + k0 + ch * 8);
        }
    }
}

__global__ __launch_bounds__(256, 2)
void gemm_mma_kernel(const float* __restrict__ b0, const float* __restrict__ b1,
                     const float* __restrict__ b2, float* __restrict__ Cout, int mode)
{
    extern __shared__ __align__(128) char smg[];
    const uint32_t sb = smem_u32(smg);
    const int tid = threadIdx.x;
    const int lane = tid & 31;
    const int wid = tid >> 5;
    const int wr = (wid >> 1) * 32;      // 0,32,64,96
    const int wn = (wid & 1) * 32;       // 0,32
    const int bm = blockIdx.y * 128;
    const int bn = blockIdx.x * 64;
    const int z = blockIdx.z;

    const int aslot = (mode == 0) ? z : 0;
    const int wslot = (mode == 0) ? z : 3;
    const __nv_bfloat16* Ah_g = g_ah + (size_t)aslot * ACTN;
    const __nv_bfloat16* Al_g = g_al + (size_t)aslot * ACTN;
    const __nv_bfloat16* Wh_g = g_wh + (size_t)wslot * WN;
    const __nv_bfloat16* Wl_g = g_wl + (size_t)wslot * WN;
    const float* bias = (mode == 1) ? b0 : (z == 0) ? b0 : (z == 1) ? b1 : b2;

    float acc[2][4][4];
#pragma unroll
    for (int a = 0; a < 2; a++)
#pragma unroll
        for (int b = 0; b < 4; b++)
#pragma unroll
            for (int c = 0; c < 4; c++) acc[a][b][c] = 0.f;

    g_load_stage(sb, 0, Ah_g, Al_g, Wh_g, Wl_g, bm, bn, 0, tid);   CP_COMMIT();
    g_load_stage(sb, 1, Ah_g, Al_g, Wh_g, Wl_g, bm, bn, GKC, tid); CP_COMMIT();

    const int NIT = DMODEL / GKC;   // 32
    const uint32_t a_row = (lane & 15);
    const uint32_t a_k8  = (lane >> 4) << 3;
    const uint32_t b_row = ((lane >> 4) << 3) + (lane & 7);
    const uint32_t b_k8  = ((lane >> 3) & 1) << 3;

    for (int it = 0; it < NIT; it++) {
        if (it == NIT - 1) { CP_WAIT(0); } else { CP_WAIT(1); }
        __syncthreads();

        if (it + 2 < NIT) {
            int s2 = (it + 2) % GNSTG;
            g_load_stage(sb, s2, Ah_g, Al_g, Wh_g, Wl_g, bm, bn, (it + 2) * GKC, tid);
            CP_COMMIT();
        }

        uint32_t base = sb + (it % GNSTG) * GASTAGE;
#pragma unroll
        for (int ks = 0; ks < 2; ks++) {
            const int k0 = ks * 16;
            uint32_t Ah[2][4], Al[2][4], Bh[2][4], Bl[2][4];
#pragma unroll
            for (int mf = 0; mf < 2; mf++) {
                uint32_t ra = base + (wr + mf * 16 + a_row) * GSTRIDE + (k0 + a_k8) * 2;
                ldsm4(ra, Ah[mf]);
                ldsm4(ra + GA_BUF, Al[mf]);
            }
#pragma unroll
            for (int np = 0; np < 2; np++) {
                uint32_t rb = base + GWOFF + (wn + np * 16 + b_row) * GSTRIDE
                              + (k0 + b_k8) * 2;
                ldsm4(rb, Bh[np]);
                ldsm4(rb + GW_BUF, Bl[np]);
            }
#pragma unroll
            for (int np = 0; np < 2; np++)
#pragma unroll
                for (int nn = 0; nn < 2; nn++)
#pragma unroll
                    for (int mf = 0; mf < 2; mf++)
                        mma_bf16(acc[mf][np * 2 + nn], Ah[mf], Bh[np] + 2 * nn);
#pragma unroll
            for (int np = 0; np < 2; np++)
#pragma unroll
                for (int nn = 0; nn < 2; nn++)
#pragma unroll
                    for (int mf = 0; mf < 2; mf++)
                        mma_bf16(acc[mf][np * 2 + nn], Ah[mf], Bl[np] + 2 * nn);
#pragma unroll
            for (int np = 0; np < 2; np++)
#pragma unroll
                for (int nn = 0; nn < 2; nn++)
#pragma unroll
                    for (int mf = 0; mf < 2; mf++)
                        mma_bf16(acc[mf][np * 2 + nn], Al[mf], Bh[np] + 2 * nn);
        }
    }

    // epilogue (q projection folded with 1/8 score scale)
    const float sc = (mode == 0 && z == 0) ? 0.125f : 1.0f;
    __nv_bfloat16* dsth = (z == 0) ? g_qh : (z == 1) ? g_kh : g_vh;
    __nv_bfloat16* dstl = (z == 0) ? g_ql : (z == 1) ? g_kl : g_vl;
#pragma unroll
    for (int mf = 0; mf < 2; mf++) {
#pragma unroll
        for (int nf = 0; nf < 4; nf++) {
            int r0 = bm + wr + mf * 16 + (lane >> 2);
            int c0 = bn + wn + nf * 8 + (lane & 3) * 2;
            float bs0 = bias[c0], bs1 = bias[c0 + 1];
#pragma unroll
            for (int hh = 0; hh < 2; hh++) {
                int row = r0 + 8 * hh;
                float v0 = (acc[mf][nf][2 * hh + 0] + bs0) * sc;
                float v1 = (acc[mf][nf][2 * hh + 1] + bs1) * sc;
                if (mode == 0) {
                    int hd = c0 >> 6, d = c0 & 63;
                    int b = row >> 11, s = row & (SEQ - 1);
                    size_t idx = ((((size_t)b * NHEAD + hd) * SEQ) + s) * DK + d;
                    uint32_t hv, lv;
                    pack_hl(v0, v1, hv, lv);
                    *(uint32_t*)&dsth[idx] = hv;
                    *(uint32_t*)&dstl[idx] = lv;
                } else {
                    float2 o = make_float2(v0, v1);
                    *(float2*)&Cout[(size_t)row * DMODEL + c0] = o;
                }
            }
        }
    }
}

// ---------------------------------------------------------------------------
// Flash attention, 3-term hi/lo mma.sync, 2-stage KV pipeline, 2 CTAs/SM.
// Q fragments reloaded from smem per k-step (register diet).
// Scores pre-scaled (Q carries 1/8). Output -> act slot 0 hi/lo.
// ---------------------------------------------------------------------------
#define ASTRIDE 144
#define AQBUF (128*ASTRIDE)          // 18432
#define AKBUF (64*ASTRIDE)           // 9216
#define ASTAGE (4*AKBUF)             // 36864
#define ANSTG 2
#define ATT_SMEM (2*AQBUF + ANSTG*ASTAGE)   // 110592

__device__ __forceinline__ void a_load_kv(uint32_t sb, int stg, int bh, int kt, int tid)
{
    uint32_t base = sb + 2 * AQBUF + stg * ASTAGE;
#pragma unroll
    for (int j = 0; j < 8; j++) {
        int g = tid + 256 * j;
        int buf = g >> 9;             // 0:Kh 1:Kl 2:Vh 3:Vl
        int cid = g & 511;
        int row = cid >> 3;
        int ch  = cid & 7;
        const __nv_bfloat16* src = (buf == 0) ? g_kh : (buf == 1) ? g_kl
                                  : (buf == 2) ? g_vh : g_vl;
        const void* gp = src + ((size_t)bh * SEQ + kt * 64 + row) * DK + ch * 8;
        cp_async16(base + buf * AKBUF + row * ASTRIDE + ch * 16, gp);
    }
}

__global__ __launch_bounds__(256, 2)
void attn_mma_kernel()
{
    extern __shared__ __align__(128) char sma[];
    const uint32_t sb = smem_u32(sma);
    const int tid = threadIdx.x;
    const int lane = tid & 31;
    const int wid = tid >> 5;
    const int bh = blockIdx.y;
    const int q0 = blockIdx.x * 128;

#pragma unroll
    for (int j = 0; j < 8; j++) {
        int g = tid + 256 * j;
        int buf = g >> 10;           // 0:Qh 1:Ql
        int cid = g & 1023;
        int row = cid >> 3;
        int ch  = cid & 7;
        const __nv_bfloat16* src = buf ? g_ql : g_qh;
        const void* gp = src + ((size_t)bh * SEQ + q0 + row) * DK + ch * 8;
        cp_async16(sb + buf * AQBUF + row * ASTRIDE + ch * 16, gp);
    }
    CP_COMMIT();
    a_load_kv(sb, 0, bh, 0, tid); CP_COMMIT();
    a_load_kv(sb, 1, bh, 1, tid); CP_COMMIT();

    const uint32_t a_row = (lane & 15);
    const uint32_t a_k8  = (lane >> 4) << 3;
    const uint32_t b_row = ((lane >> 4) << 3) + (lane & 7);
    const uint32_t b_k8  = ((lane >> 3) & 1) << 3;
    const uint32_t v_row = (((lane >> 3) & 1) << 3) + (lane & 7);
    const uint32_t v_c8  = (lane >> 4) << 3;
    const int wq = wid * 16;

    float o[8][4];
#pragma unroll
    for (int i = 0; i < 8; i++)
#pragma unroll
        for (int k = 0; k < 4; k++) o[i][k] = 0.f;
    float m0 = -INFINITY, m1 = -INFINITY, l0 = 0.f, l1 = 0.f;

    const int NT = SEQ / 64;   // 32
    for (int it = 0; it < NT; it++) {
        if (it == NT - 1) { CP_WAIT(0); } else { CP_WAIT(1); }
        __syncthreads();
        uint32_t kb = sb + 2 * AQBUF + (it & 1) * ASTAGE;

        // ---- S = Q K^T (Q pre-scaled by 1/8) ----
        float s[8][4];
#pragma unroll
        for (int i = 0; i < 8; i++)
#pragma unroll
            for (int k = 0; k < 4; k++) s[i][k] = 0.f;

#pragma unroll
        for (int ks = 0; ks < 4; ks++) {
            uint32_t ra = sb + (wq + a_row) * ASTRIDE + (ks * 16 + a_k8) * 2;
            uint32_t Qh[4], Ql[4];
            ldsm4(ra, Qh);
            ldsm4(ra + AQBUF, Ql);
#pragma unroll
            for (int np = 0; np < 4; np++) {
                uint32_t rb = kb + (np * 16 + b_row) * ASTRIDE + (ks * 16 + b_k8) * 2;
                uint32_t Bh[4], Bl[4];
                ldsm4(rb, Bh);
                ldsm4(rb + AKBUF, Bl);
#pragma unroll
                for (int nn = 0; nn < 2; nn++)
                    mma_bf16(s[np * 2 + nn], Qh, Bh + 2 * nn);
#pragma unroll
                for (int nn = 0; nn < 2; nn++)
                    mma_bf16(s[np * 2 + nn], Qh, Bl + 2 * nn);
#pragma unroll
                for (int nn = 0; nn < 2; nn++)
                    mma_bf16(s[np * 2 + nn], Ql, Bh + 2 * nn);
            }
        }

        // ---- online softmax ----
        float mx0 = -INFINITY, mx1 = -INFINITY;
#pragma unroll
        for (int i = 0; i < 8; i++) {
            mx0 = fmaxf(mx0, fmaxf(s[i][0], s[i][1]));
            mx1 = fmaxf(mx1, fmaxf(s[i][2], s[i][3]));
        }
        mx0 = fmaxf(mx0, __shfl_xor_sync(0xffffffffu, mx0, 1));
        mx0 = fmaxf(mx0, __shfl_xor_sync(0xffffffffu, mx0, 2));
        mx1 = fmaxf(mx1, __shfl_xor_sync(0xffffffffu, mx1, 1));
        mx1 = fmaxf(mx1, __shfl_xor_sync(0xffffffffu, mx1, 2));

        float mn0 = fmaxf(m0, mx0), mn1 = fmaxf(m1, mx1);
        float al0 = __expf(m0 - mn0), al1 = __expf(m1 - mn1);
        m0 = mn0; m1 = mn1;

        float rs0 = 0.f, rs1 = 0.f;
#pragma unroll
        for (int i = 0; i < 8; i++) {
            s[i][0] = __expf(s[i][0] - mn0);
            s[i][1] = __expf(s[i][1] - mn0);
            s[i][2] = __expf(s[i][2] - mn1);
            s[i][3] = __expf(s[i][3] - mn1);
            rs0 += s[i][0] + s[i][1];
            rs1 += s[i][2] + s[i][3];
        }
        rs0 += __shfl_xor_sync(0xffffffffu, rs0, 1);
        rs0 += __shfl_xor_sync(0xffffffffu, rs0, 2);
        rs1 += __shfl_xor_sync(0xffffffffu, rs1, 1);
        rs1 += __shfl_xor_sync(0xffffffffu, rs1, 2);
        l0 = l0 * al0 + rs0;
        l1 = l1 * al1 + rs1;
#pragma unroll
        for (int i = 0; i < 8; i++) {
            o[i][0] *= al0; o[i][1] *= al0;
            o[i][2] *= al1; o[i][3] *= al1;
        }

        // ---- repack P (hi/lo A-frags) ----
        uint32_t Ph[4][4], Pl[4][4];
#pragma unroll
        for (int j = 0; j < 4; j++) {
            pack_hl(s[2*j][0],   s[2*j][1],   Ph[j][0], Pl[j][0]);
            pack_hl(s[2*j][2],   s[2*j][3],   Ph[j][1], Pl[j][1]);
            pack_hl(s[2*j+1][0], s[2*j+1][1], Ph[j][2], Pl[j][2]);
            pack_hl(s[2*j+1][2], s[2*j+1][3], Ph[j][3], Pl[j][3]);
        }

        // ---- O += P V ----
#pragma unroll
        for (int j = 0; j < 4; j++) {
#pragma unroll
            for (int np = 0; np < 4; np++) {
                uint32_t rv = kb + 2 * AKBUF + (j * 16 + v_row) * ASTRIDE
                              + (np * 16 + v_c8) * 2;
                uint32_t Vh[4], Vl[4];
                ldsm4t(rv, Vh);
                ldsm4t(rv + AKBUF, Vl);
#pragma unroll
                for (int nn = 0; nn < 2; nn++)
                    mma_bf16(o[np * 2 + nn], Ph[j], Vh + 2 * nn);
#pragma unroll
                for (int nn = 0; nn < 2; nn++)
                    mma_bf16(o[np * 2 + nn], Ph[j], Vl + 2 * nn);
#pragma unroll
                for (int nn = 0; nn < 2; nn++)
                    mma_bf16(o[np * 2 + nn], Pl[j], Vh + 2 * nn);
            }
        }

        __syncthreads();
        if (it + 2 < NT) {
            a_load_kv(sb, it & 1, bh, it + 2, tid);
            CP_COMMIT();
        }
    }

    // ---- epilogue: x hi/lo into act slot 0 ----
    float inv0 = 1.0f / l0, inv1 = 1.0f / l1;
    const int b = bh >> 4;
    const int h = bh & (NHEAD - 1);
    const int qrow = q0 + wid * 16 + (lane >> 2);
#pragma unroll
    for (int nf = 0; nf < 8; nf++) {
        int d = h * DK + nf * 8 + (lane & 3) * 2;
        uint32_t hv, lv;
        size_t idx0 = ((size_t)b * SEQ + qrow) * DMODEL + d;
        pack_hl(o[nf][0] * inv0, o[nf][1] * inv0, hv, lv);
        *(uint32_t*)&g_ah[idx0] = hv;
        *(uint32_t*)&g_al[idx0] = lv;
        size_t idx1 = ((size_t)b * SEQ + qrow + 8) * DMODEL + d;
        pack_hl(o[nf][2] * inv1, o[nf][3] * inv1, hv, lv);
        *(uint32_t*)&g_ah[idx1] = hv;
        *(uint32_t*)&g_al[idx1] = lv;
    }
}

// ---------------------------------------------------------------------------
extern "C" void kernel_launch(void* const* d_in, const int* in_sizes, int n_in,
                              void* d_out, int out_size)
{
    (void)in_sizes; (void)n_in; (void)out_size;
    const float* query = (const float*)d_in[0];
    const float* key   = (const float*)d_in[1];
    const float* value = (const float*)d_in[2];
    const float* Wq = (const float*)d_in[3];
    const float* bq = (const float*)d_in[4];
    const float* Wk = (const float*)d_in[5];
    const float* bk = (const float*)d_in[6];
    const float* Wv = (const float*)d_in[7];
    const float* bv = (const float*)d_in[8];
    const float* Wo = (const float*)d_in[9];
    const float* bo = (const float*)d_in[10];
    float* out = (float*)d_out;

    cudaFuncSetAttribute(gemm_mma_kernel, cudaFuncAttributeMaxDynamicSharedMemorySize,
                         GEMM_SMEM);
    cudaFuncSetAttribute(attn_mma_kernel, cudaFuncAttributeMaxDynamicSharedMemorySize,
                         ATT_SMEM);

    const int nA4 = (int)(ACTN / 4);
    const int nW4 = (int)(WN / 4);

    cvt_w_kernel<<<dim3(nW4 / 256, 4), 256>>>(Wq, Wk, Wv, Wo, nW4);
    cvt_act_kernel<<<dim3(nA4 / 256, 3), 256>>>(query, key, value, nA4);

    gemm_mma_kernel<<<dim3(16, 64, 3), 256, GEMM_SMEM>>>(bq, bk, bv, nullptr, 0);

    attn_mma_kernel<<<dim3(SEQ / 128, BATCH * NHEAD), 256, ATT_SMEM>>>();

    gemm_mma_kernel<<<dim3(16, 64, 1), 256, GEMM_SMEM>>>(bo, bo, bo, out, 1);
}

// round 7
// speedup vs baseline: 4.6327x; 1.4969x over previous
#include <cuda_runtime.h>
#include <cuda_fp16.h>
#include <math.h>
#include <stdint.h>

#define NHEAD 16
#define DK 64
#define DMODEL 1024
#define BATCH 4
#define SEQ 2048
#define MTOT (BATCH*SEQ)                  // 8192
#define ACTN ((size_t)MTOT*DMODEL)
#define WN   ((size_t)DMODEL*DMODEL)
#define HS   ((size_t)BATCH*NHEAD*SEQ*DK)

// act slots: 0=query/x, 1=key, 2=value (hi/lo split); weights: single fp16, 4 slots
__device__ __half g_ah[3*ACTN];
__device__ __half g_al[3*ACTN];
__device__ __half g_w [4*WN];
__device__ __half g_qh[HS], g_ql[HS];     // Q split (scaled by 1/8)
__device__ __half g_k [HS];               // K single-rounded
__device__ __half g_vh[HS], g_vl[HS];     // V split

// ---------------- helpers ----------------
__device__ __forceinline__ uint32_t smem_u32(const void* p) {
    uint32_t a;
    asm("{ .reg .u64 t; cvta.to.shared.u64 t, %1; cvt.u32.u64 %0, t; }" : "=r"(a) : "l"(p));
    return a;
}
__device__ __forceinline__ void cp_async16(uint32_t dst, const void* src) {
    asm volatile("cp.async.cg.shared.global [%0], [%1], 16;" :: "r"(dst), "l"(src));
}
#define CP_COMMIT() asm volatile("cp.async.commit_group;" ::: "memory")
#define CP_WAIT(n)  asm volatile("cp.async.wait_group %0;" :: "n"(n) : "memory")

__device__ __forceinline__ void ldsm4(uint32_t a, uint32_t* r) {
    asm volatile("ldmatrix.sync.aligned.m8n8.x4.shared.b16 {%0,%1,%2,%3}, [%4];"
        : "=r"(r[0]), "=r"(r[1]), "=r"(r[2]), "=r"(r[3]) : "r"(a));
}
__device__ __forceinline__ void ldsm4t(uint32_t a, uint32_t* r) {
    asm volatile("ldmatrix.sync.aligned.m8n8.x4.trans.shared.b16 {%0,%1,%2,%3}, [%4];"
        : "=r"(r[0]), "=r"(r[1]), "=r"(r[2]), "=r"(r[3]) : "r"(a));
}
__device__ __forceinline__ void mma_f16(float* c, const uint32_t* a, const uint32_t* b) {
    asm volatile("mma.sync.aligned.m16n8k16.row.col.f32.f16.f16.f32 "
        "{%0,%1,%2,%3}, {%4,%5,%6,%7}, {%8,%9}, {%0,%1,%2,%3};"
        : "+f"(c[0]), "+f"(c[1]), "+f"(c[2]), "+f"(c[3])
        : "r"(a[0]), "r"(a[1]), "r"(a[2]), "r"(a[3]), "r"(b[0]), "r"(b[1]));
}
__device__ __forceinline__ uint32_t pack_h(float p0, float p1) {
    __half2 hv = __floats2half2_rn(p0, p1);
    return *(uint32_t*)&hv;
}
__device__ __forceinline__ void pack_hl(float p0, float p1, uint32_t& h, uint32_t& l) {
    __half2 hv = __floats2half2_rn(p0, p1);
    __half2 lv = __floats2half2_rn(p0 - __low2float(hv), p1 - __high2float(hv));
    h = *(uint32_t*)&hv;
    l = *(uint32_t*)&lv;
}

// ---------------------------------------------------------------------------
// fp32 -> fp16 converts
// ---------------------------------------------------------------------------
__global__ void cvt_act_kernel(const float* __restrict__ q, const float* __restrict__ k,
                               const float* __restrict__ v, int n4)
{
    int z = blockIdx.y;
    const float* src = (z == 0) ? q : (z == 1) ? k : v;
    __half* hi = g_ah + (size_t)z * ACTN;
    __half* lo = g_al + (size_t)z * ACTN;
    int i = blockIdx.x * blockDim.x + threadIdx.x;
    if (i >= n4) return;
    float4 vv = ((const float4*)src)[i];
    uint32_t h0, l0, h1, l1;
    pack_hl(vv.x, vv.y, h0, l0);
    pack_hl(vv.z, vv.w, h1, l1);
    ((uint32_t*)hi)[2*i]   = h0;
    ((uint32_t*)hi)[2*i+1] = h1;
    ((uint32_t*)lo)[2*i]   = l0;
    ((uint32_t*)lo)[2*i+1] = l1;
}

__global__ void cvt_w_kernel(const float* __restrict__ w0, const float* __restrict__ w1,
                             const float* __restrict__ w2, const float* __restrict__ w3,
                             int n4)
{
    int z = blockIdx.y;
    const float* src = (z == 0) ? w0 : (z == 1) ? w1 : (z == 2) ? w2 : w3;
    __half* hi = g_w + (size_t)z * WN;
    int i = blockIdx.x * blockDim.x + threadIdx.x;
    if (i >= n4) return;
    float4 vv = ((const float4*)src)[i];
    ((uint32_t*)hi)[2*i]   = pack_h(vv.x, vv.y);
    ((uint32_t*)hi)[2*i+1] = pack_h(vv.z, vv.w);
}

// ---------------------------------------------------------------------------
// GEMM: C = (Ah+Al) @ W^T + bias, fp16 2-term mma.sync.
// CTA 128x128, K-chunk 32, 3-stage pipeline, 2 CTAs/SM.
// 8 warps 4(M)x2(N), warp tile 32x64.
// mode 0: fused QKV (z: 0->Q split scaled, 1->K single, 2->V split).
// mode 1: final projection -> fp32 out.
// ---------------------------------------------------------------------------
#define GKC 32
#define GSTRIDE 80                 // 32 fp16 = 64B + 16B pad
#define GA_BUF (128*GSTRIDE)       // 10240
#define GASTAGE (3*GA_BUF)         // Ah, Al, W = 30720
#define GNSTG 3
#define GEMM_SMEM (GNSTG*GASTAGE)  // 92160

__device__ __forceinline__ void g_load_stage(uint32_t sb, int stg,
                                             const __half* Ah_g, const __half* Al_g,
                                             const __half* W_g,
                                             int bm, int bn, int k0, int tid)
{
    uint32_t base = sb + stg * GASTAGE;
#pragma unroll
    for (int j = 0; j < 6; j++) {
        int g = tid + 256 * j;            // 0..1535
        int buf = g >> 9;                 // 0:Ah 1:Al 2:W
        int cid = g & 511;
        int row = cid >> 2;
        int ch  = cid & 3;
        const __half* src = (buf == 0) ? Ah_g : (buf == 1) ? Al_g : W_g;
        int rbase = (buf < 2) ? bm : bn;
        cp_async16(base + buf * GA_BUF + row * GSTRIDE + ch * 16,
                   src + (size_t)(rbase + row) * DMODEL + k0 + ch * 8);
    }
}

__global__ __launch_bounds__(256, 2)
void gemm_mma_kernel(const float* __restrict__ b0, const float* __restrict__ b1,
                     const float* __restrict__ b2, float* __restrict__ Cout, int mode)
{
    extern __shared__ __align__(128) char smg[];
    const uint32_t sb = smem_u32(smg);
    const int tid = threadIdx.x;
    const int lane = tid & 31;
    const int wid = tid >> 5;
    const int wr = (wid >> 1) * 32;      // 0,32,64,96
    const int wn = (wid & 1) * 64;       // 0,64
    const int bm = blockIdx.y * 128;
    const int bn = blockIdx.x * 128;
    const int z = blockIdx.z;

    const int aslot = (mode == 0) ? z : 0;
    const int wslot = (mode == 0) ? z : 3;
    const __half* Ah_g = g_ah + (size_t)aslot * ACTN;
    const __half* Al_g = g_al + (size_t)aslot * ACTN;
    const __half* W_g  = g_w  + (size_t)wslot * WN;
    const float* bias = (mode == 1) ? b0 : (z == 0) ? b0 : (z == 1) ? b1 : b2;

    float acc[2][8][4];
#pragma unroll
    for (int a = 0; a < 2; a++)
#pragma unroll
        for (int b = 0; b < 8; b++)
#pragma unroll
            for (int c = 0; c < 4; c++) acc[a][b][c] = 0.f;

    g_load_stage(sb, 0, Ah_g, Al_g, W_g, bm, bn, 0, tid);   CP_COMMIT();
    g_load_stage(sb, 1, Ah_g, Al_g, W_g, bm, bn, GKC, tid); CP_COMMIT();

    const int NIT = DMODEL / GKC;   // 32
    const uint32_t a_row = (lane & 15);
    const uint32_t a_k8  = (lane >> 4) << 3;
    const uint32_t b_row = ((lane >> 4) << 3) + (lane & 7);
    const uint32_t b_k8  = ((lane >> 3) & 1) << 3;

    for (int it = 0; it < NIT; it++) {
        if (it == NIT - 1) { CP_WAIT(0); } else { CP_WAIT(1); }
        __syncthreads();

        if (it + 2 < NIT) {
            g_load_stage(sb, (it + 2) % GNSTG, Ah_g, Al_g, W_g, bm, bn,
                         (it + 2) * GKC, tid);
            CP_COMMIT();
        }

        uint32_t base = sb + (it % GNSTG) * GASTAGE;
#pragma unroll
        for (int ks = 0; ks < 2; ks++) {
            const int k0 = ks * 16;
            uint32_t Ah[2][4], Al[2][4], Bf[4][4];
#pragma unroll
            for (int mf = 0; mf < 2; mf++) {
                uint32_t ra = base + (wr + mf * 16 + a_row) * GSTRIDE + (k0 + a_k8) * 2;
                ldsm4(ra, Ah[mf]);
                ldsm4(ra + GA_BUF, Al[mf]);
            }
#pragma unroll
            for (int np = 0; np < 4; np++) {
                uint32_t rb = base + 2 * GA_BUF + (wn + np * 16 + b_row) * GSTRIDE
                              + (k0 + b_k8) * 2;
                ldsm4(rb, Bf[np]);
            }
#pragma unroll
            for (int np = 0; np < 4; np++)
#pragma unroll
                for (int nn = 0; nn < 2; nn++)
#pragma unroll
                    for (int mf = 0; mf < 2; mf++)
                        mma_f16(acc[mf][np * 2 + nn], Ah[mf], Bf[np] + 2 * nn);
#pragma unroll
            for (int np = 0; np < 4; np++)
#pragma unroll
                for (int nn = 0; nn < 2; nn++)
#pragma unroll
                    for (int mf = 0; mf < 2; mf++)
                        mma_f16(acc[mf][np * 2 + nn], Al[mf], Bf[np] + 2 * nn);
        }
    }

    // epilogue
    const float sc = (mode == 0 && z == 0) ? 0.125f : 1.0f;
#pragma unroll
    for (int mf = 0; mf < 2; mf++) {
#pragma unroll
        for (int nf = 0; nf < 8; nf++) {
            int r0 = bm + wr + mf * 16 + (lane >> 2);
            int c0 = bn + wn + nf * 8 + (lane & 3) * 2;
            float bs0 = bias[c0], bs1 = bias[c0 + 1];
#pragma unroll
            for (int hh = 0; hh < 2; hh++) {
                int row = r0 + 8 * hh;
                float v0 = (acc[mf][nf][2 * hh + 0] + bs0) * sc;
                float v1 = (acc[mf][nf][2 * hh + 1] + bs1) * sc;
                if (mode == 0) {
                    int hd = c0 >> 6, d = c0 & 63;
                    int b = row >> 11, s = row & (SEQ - 1);
                    size_t idx = ((((size_t)b * NHEAD + hd) * SEQ) + s) * DK + d;
                    if (z == 1) {
                        *(uint32_t*)&g_k[idx] = pack_h(v0, v1);
                    } else {
                        uint32_t hv, lv;
                        pack_hl(v0, v1, hv, lv);
                        if (z == 0) {
                            *(uint32_t*)&g_qh[idx] = hv;
                            *(uint32_t*)&g_ql[idx] = lv;
                        } else {
                            *(uint32_t*)&g_vh[idx] = hv;
                            *(uint32_t*)&g_vl[idx] = lv;
                        }
                    }
                } else {
                    float2 o = make_float2(v0, v1);
                    *(float2*)&Cout[(size_t)row * DMODEL + c0] = o;
                }
            }
        }
    }
}

// ---------------------------------------------------------------------------
// Flash attention, fp16 2-term: S = (Qh+Ql)K^T, O = P(Vh+Vl), P single-rounded.
// 2-stage KV pipeline, 2 CTAs/SM. Output -> act slot 0 hi/lo.
// ---------------------------------------------------------------------------
#define ASTRIDE 144
#define AQBUF (128*ASTRIDE)          // 18432
#define AKBUF (64*ASTRIDE)           // 9216
#define ASTAGE (3*AKBUF)             // K, Vh, Vl = 27648
#define ANSTG 2
#define ATT_SMEM (2*AQBUF + ANSTG*ASTAGE)   // 92160

__device__ __forceinline__ void a_load_kv(uint32_t sb, int stg, int bh, int kt, int tid)
{
    uint32_t base = sb + 2 * AQBUF + stg * ASTAGE;
#pragma unroll
    for (int j = 0; j < 6; j++) {
        int g = tid + 256 * j;        // 0..1535
        int buf = g >> 9;             // 0:K 1:Vh 2:Vl
        int cid = g & 511;
        int row = cid >> 3;
        int ch  = cid & 7;
        const __half* src = (buf == 0) ? g_k : (buf == 1) ? g_vh : g_vl;
        const void* gp = src + ((size_t)bh * SEQ + kt * 64 + row) * DK + ch * 8;
        cp_async16(base + buf * AKBUF + row * ASTRIDE + ch * 16, gp);
    }
}

__global__ __launch_bounds__(256, 2)
void attn_mma_kernel()
{
    extern __shared__ __align__(128) char sma[];
    const uint32_t sb = smem_u32(sma);
    const int tid = threadIdx.x;
    const int lane = tid & 31;
    const int wid = tid >> 5;
    const int bh = blockIdx.y;
    const int q0 = blockIdx.x * 128;

    // Q tile hi/lo
#pragma unroll
    for (int j = 0; j < 8; j++) {
        int g = tid + 256 * j;
        int buf = g >> 10;           // 0:Qh 1:Ql
        int cid = g & 1023;
        int row = cid >> 3;
        int ch  = cid & 7;
        const __half* src = buf ? g_ql : g_qh;
        const void* gp = src + ((size_t)bh * SEQ + q0 + row) * DK + ch * 8;
        cp_async16(sb + buf * AQBUF + row * ASTRIDE + ch * 16, gp);
    }
    CP_COMMIT();
    a_load_kv(sb, 0, bh, 0, tid); CP_COMMIT();
    a_load_kv(sb, 1, bh, 1, tid); CP_COMMIT();

    const uint32_t a_row = (lane & 15);
    const uint32_t a_k8  = (lane >> 4) << 3;
    const uint32_t b_row = ((lane >> 4) << 3) + (lane & 7);
    const uint32_t b_k8  = ((lane >> 3) & 1) << 3;
    const uint32_t v_row = (((lane >> 3) & 1) << 3) + (lane & 7);
    const uint32_t v_c8  = (lane >> 4) << 3;
    const int wq = wid * 16;

    float o[8][4];
#pragma unroll
    for (int i = 0; i < 8; i++)
#pragma unroll
        for (int k = 0; k < 4; k++) o[i][k] = 0.f;
    float m0 = -INFINITY, m1 = -INFINITY, l0 = 0.f, l1 = 0.f;

    const int NT = SEQ / 64;   // 32
    for (int it = 0; it < NT; it++) {
        if (it == NT - 1) { CP_WAIT(0); } else { CP_WAIT(1); }
        __syncthreads();
        uint32_t kb = sb + 2 * AQBUF + (it & 1) * ASTAGE;

        // ---- S = (Qh+Ql) K^T  (Q carries 1/8 scale) ----
        float s[8][4];
#pragma unroll
        for (int i = 0; i < 8; i++)
#pragma unroll
            for (int k = 0; k < 4; k++) s[i][k] = 0.f;

#pragma unroll
        for (int ks = 0; ks < 4; ks++) {
            uint32_t ra = sb + (wq + a_row) * ASTRIDE + (ks * 16 + a_k8) * 2;
            uint32_t Qh[4], Ql[4];
            ldsm4(ra, Qh);
            ldsm4(ra + AQBUF, Ql);
#pragma unroll
            for (int np = 0; np < 4; np++) {
                uint32_t rb = kb + (np * 16 + b_row) * ASTRIDE + (ks * 16 + b_k8) * 2;
                uint32_t Kf[4];
                ldsm4(rb, Kf);
#pragma unroll
                for (int nn = 0; nn < 2; nn++)
                    mma_f16(s[np * 2 + nn], Qh, Kf + 2 * nn);
#pragma unroll
                for (int nn = 0; nn < 2; nn++)
                    mma_f16(s[np * 2 + nn], Ql, Kf + 2 * nn);
            }
        }

        // ---- online softmax ----
        float mx0 = -INFINITY, mx1 = -INFINITY;
#pragma unroll
        for (int i = 0; i < 8; i++) {
            mx0 = fmaxf(mx0, fmaxf(s[i][0], s[i][1]));
            mx1 = fmaxf(mx1, fmaxf(s[i][2], s[i][3]));
        }
        mx0 = fmaxf(mx0, __shfl_xor_sync(0xffffffffu, mx0, 1));
        mx0 = fmaxf(mx0, __shfl_xor_sync(0xffffffffu, mx0, 2));
        mx1 = fmaxf(mx1, __shfl_xor_sync(0xffffffffu, mx1, 1));
        mx1 = fmaxf(mx1, __shfl_xor_sync(0xffffffffu, mx1, 2));

        float mn0 = fmaxf(m0, mx0), mn1 = fmaxf(m1, mx1);
        float al0 = __expf(m0 - mn0), al1 = __expf(m1 - mn1);
        m0 = mn0; m1 = mn1;

        float rs0 = 0.f, rs1 = 0.f;
#pragma unroll
        for (int i = 0; i < 8; i++) {
            s[i][0] = __expf(s[i][0] - mn0);
            s[i][1] = __expf(s[i][1] - mn0);
            s[i][2] = __expf(s[i][2] - mn1);
            s[i][3] = __expf(s[i][3] - mn1);
            rs0 += s[i][0] + s[i][1];
            rs1 += s[i][2] + s[i][3];
        }
        rs0 += __shfl_xor_sync(0xffffffffu, rs0, 1);
        rs0 += __shfl_xor_sync(0xffffffffu, rs0, 2);
        rs1 += __shfl_xor_sync(0xffffffffu, rs1, 1);
        rs1 += __shfl_xor_sync(0xffffffffu, rs1, 2);
        l0 = l0 * al0 + rs0;
        l1 = l1 * al1 + rs1;
#pragma unroll
        for (int i = 0; i < 8; i++) {
            o[i][0] *= al0; o[i][1] *= al0;
            o[i][2] *= al1; o[i][3] *= al1;
        }

        // ---- P single-rounded fp16 A-frags ----
        uint32_t Pf[4][4];
#pragma unroll
        for (int j = 0; j < 4; j++) {
            Pf[j][0] = pack_h(s[2*j][0],   s[2*j][1]);
            Pf[j][1] = pack_h(s[2*j][2],   s[2*j][3]);
            Pf[j][2] = pack_h(s[2*j+1][0], s[2*j+1][1]);
            Pf[j][3] = pack_h(s[2*j+1][2], s[2*j+1][3]);
        }

        // ---- O += P (Vh+Vl) ----
#pragma unroll
        for (int j = 0; j < 4; j++) {
#pragma unroll
            for (int np = 0; np < 4; np++) {
                uint32_t rv = kb + AKBUF + (j * 16 + v_row) * ASTRIDE
                              + (np * 16 + v_c8) * 2;
                uint32_t Vh[4], Vl[4];
                ldsm4t(rv, Vh);
                ldsm4t(rv + AKBUF, Vl);
#pragma unroll
                for (int nn = 0; nn < 2; nn++)
                    mma_f16(o[np * 2 + nn], Pf[j], Vh + 2 * nn);
#pragma unroll
                for (int nn = 0; nn < 2; nn++)
                    mma_f16(o[np * 2 + nn], Pf[j], Vl + 2 * nn);
            }
        }

        __syncthreads();
        if (it + 2 < NT) {
            a_load_kv(sb, it & 1, bh, it + 2, tid);
            CP_COMMIT();
        }
    }

    // ---- epilogue: x hi/lo into act slot 0 ----
    float inv0 = 1.0f / l0, inv1 = 1.0f / l1;
    const int b = bh >> 4;
    const int h = bh & (NHEAD - 1);
    const int qrow = q0 + wid * 16 + (lane >> 2);
#pragma unroll
    for (int nf = 0; nf < 8; nf++) {
        int d = h * DK + nf * 8 + (lane & 3) * 2;
        uint32_t hv, lv;
        size_t idx0 = ((size_t)b * SEQ + qrow) * DMODEL + d;
        pack_hl(o[nf][0] * inv0, o[nf][1] * inv0, hv, lv);
        *(uint32_t*)&g_ah[idx0] = hv;
        *(uint32_t*)&g_al[idx0] = lv;
        size_t idx1 = ((size_t)b * SEQ + qrow + 8) * DMODEL + d;
        pack_hl(o[nf][2] * inv1, o[nf][3] * inv1, hv, lv);
        *(uint32_t*)&g_ah[idx1] = hv;
        *(uint32_t*)&g_al[idx1] = lv;
    }
}

// ---------------------------------------------------------------------------
extern "C" void kernel_launch(void* const* d_in, const int* in_sizes, int n_in,
                              void* d_out, int out_size)
{
    (void)in_sizes; (void)n_in; (void)out_size;
    const float* query = (const float*)d_in[0];
    const float* key   = (const float*)d_in[1];
    const float* value = (const float*)d_in[2];
    const float* Wq = (const float*)d_in[3];
    const float* bq = (const float*)d_in[4];
    const float* Wk = (const float*)d_in[5];
    const float* bk = (const float*)d_in[6];
    const float* Wv = (const float*)d_in[7];
    const float* bv = (const float*)d_in[8];
    const float* Wo = (const float*)d_in[9];
    const float* bo = (const float*)d_in[10];
    float* out = (float*)d_out;

    cudaFuncSetAttribute(gemm_mma_kernel, cudaFuncAttributeMaxDynamicSharedMemorySize,
                         GEMM_SMEM);
    cudaFuncSetAttribute(attn_mma_kernel, cudaFuncAttributeMaxDynamicSharedMemorySize,
                         ATT_SMEM);

    const int nA4 = (int)(ACTN / 4);
    const int nW4 = (int)(WN / 4);

    cvt_w_kernel<<<dim3(nW4 / 256, 4), 256>>>(Wq, Wk, Wv, Wo, nW4);
    cvt_act_kernel<<<dim3(nA4 / 256, 3), 256>>>(query, key, value, nA4);

    gemm_mma_kernel<<<dim3(8, 64, 3), 256, GEMM_SMEM>>>(bq, bk, bv, nullptr, 0);

    attn_mma_kernel<<<dim3(SEQ / 128, BATCH * NHEAD), 256, ATT_SMEM>>>();

    gemm_mma_kernel<<<dim3(8, 64, 1), 256, GEMM_SMEM>>>(bo, bo, bo, out, 1);
}

// round 9
// speedup vs baseline: 4.6640x; 1.0067x over previous
#include <cuda_runtime.h>
#include <cuda_fp16.h>
#include <math.h>
#include <stdint.h>

#define NHEAD 16
#define DK 64
#define DMODEL 1024
#define BATCH 4
#define SEQ 2048
#define MTOT (BATCH*SEQ)                  // 8192
#define ACTN ((size_t)MTOT*DMODEL)
#define WN   ((size_t)DMODEL*DMODEL)
#define HS   ((size_t)BATCH*NHEAD*SEQ*DK)

// act slots: 0=query/x, 1=key, 2=value (hi/lo split); weights single fp16
__device__ __half g_ah[3*ACTN];
__device__ __half g_al[3*ACTN];
__device__ __half g_w [4*WN];
__device__ __half g_qh[HS], g_ql[HS];     // Q split (scaled by 1/8)
__device__ __half g_k [HS];               // K single-rounded
__device__ __half g_v [HS];               // V single-rounded

// ---------------- helpers ----------------
__device__ __forceinline__ uint32_t smem_u32(const void* p) {
    uint32_t a;
    asm("{ .reg .u64 t; cvta.to.shared.u64 t, %1; cvt.u32.u64 %0, t; }" : "=r"(a) : "l"(p));
    return a;
}
__device__ __forceinline__ void cp_async16(uint32_t dst, const void* src) {
    asm volatile("cp.async.cg.shared.global [%0], [%1], 16;" :: "r"(dst), "l"(src));
}
#define CP_COMMIT() asm volatile("cp.async.commit_group;" ::: "memory")
#define CP_WAIT(n)  asm volatile("cp.async.wait_group %0;" :: "n"(n) : "memory")

__device__ __forceinline__ void ldsm4(uint32_t a, uint32_t* r) {
    asm volatile("ldmatrix.sync.aligned.m8n8.x4.shared.b16 {%0,%1,%2,%3}, [%4];"
        : "=r"(r[0]), "=r"(r[1]), "=r"(r[2]), "=r"(r[3]) : "r"(a));
}
__device__ __forceinline__ void ldsm4t(uint32_t a, uint32_t* r) {
    asm volatile("ldmatrix.sync.aligned.m8n8.x4.trans.shared.b16 {%0,%1,%2,%3}, [%4];"
        : "=r"(r[0]), "=r"(r[1]), "=r"(r[2]), "=r"(r[3]) : "r"(a));
}
__device__ __forceinline__ void mma_f16(float* c, const uint32_t* a, const uint32_t* b) {
    asm volatile("mma.sync.aligned.m16n8k16.row.col.f32.f16.f16.f32 "
        "{%0,%1,%2,%3}, {%4,%5,%6,%7}, {%8,%9}, {%0,%1,%2,%3};"
        : "+f"(c[0]), "+f"(c[1]), "+f"(c[2]), "+f"(c[3])
        : "r"(a[0]), "r"(a[1]), "r"(a[2]), "r"(a[3]), "r"(b[0]), "r"(b[1]));
}
__device__ __forceinline__ uint32_t pack_h(float p0, float p1) {
    __half2 hv = __floats2half2_rn(p0, p1);
    return *(uint32_t*)&hv;
}
__device__ __forceinline__ void pack_hl(float p0, float p1, uint32_t& h, uint32_t& l) {
    __half2 hv = __floats2half2_rn(p0, p1);
    __half2 lv = __floats2half2_rn(p0 - __low2float(hv), p1 - __high2float(hv));
    h = *(uint32_t*)&hv;
    l = *(uint32_t*)&lv;
}

// ---------------------------------------------------------------------------
// fp32 -> fp16 converts
// ---------------------------------------------------------------------------
__global__ void cvt_act_kernel(const float* __restrict__ q, const float* __restrict__ k,
                               const float* __restrict__ v, int n4)
{
    int z = blockIdx.y;
    const float* src = (z == 0) ? q : (z == 1) ? k : v;
    __half* hi = g_ah + (size_t)z * ACTN;
    __half* lo = g_al + (size_t)z * ACTN;
    int i = blockIdx.x * blockDim.x + threadIdx.x;
    if (i >= n4) return;
    float4 vv = ((const float4*)src)[i];
    uint32_t h0, l0, h1, l1;
    pack_hl(vv.x, vv.y, h0, l0);
    pack_hl(vv.z, vv.w, h1, l1);
    ((uint32_t*)hi)[2*i]   = h0;
    ((uint32_t*)hi)[2*i+1] = h1;
    ((uint32_t*)lo)[2*i]   = l0;
    ((uint32_t*)lo)[2*i+1] = l1;
}

__global__ void cvt_w_kernel(const float* __restrict__ w0, const float* __restrict__ w1,
                             const float* __restrict__ w2, const float* __restrict__ w3,
                             int n4)
{
    int z = blockIdx.y;
    const float* src = (z == 0) ? w0 : (z == 1) ? w1 : (z == 2) ? w2 : w3;
    __half* hi = g_w + (size_t)z * WN;
    int i = blockIdx.x * blockDim.x + threadIdx.x;
    if (i >= n4) return;
    float4 vv = ((const float4*)src)[i];
    ((uint32_t*)hi)[2*i]   = pack_h(vv.x, vv.y);
    ((uint32_t*)hi)[2*i+1] = pack_h(vv.z, vv.w);
}

// ---------------------------------------------------------------------------
// GEMM: C = (Ah+Al) @ W^T + bias, fp16 2-term mma.sync.
// CTA 128x128, K-chunk 32, 3-stage, 2 CTAs/SM. 8 warps 4(M)x2(N), warp 32x64.
// mode 0 z: 0->Q split scaled, 1->K single, 2->V single. mode 1: fp32 out.
// ---------------------------------------------------------------------------
#define GKC 32
#define GSTRIDE 80
#define GA_BUF (128*GSTRIDE)       // 10240
#define GASTAGE (3*GA_BUF)         // Ah, Al, W
#define GNSTG 3
#define GEMM_SMEM (GNSTG*GASTAGE)  // 92160

__device__ __forceinline__ void g_load_stage(uint32_t sb, int stg,
                                             const __half* Ah_g, const __half* Al_g,
                                             const __half* W_g,
                                             int bm, int bn, int k0, int tid)
{
    uint32_t base = sb + stg * GASTAGE;
#pragma unroll
    for (int j = 0; j < 6; j++) {
        int g = tid + 256 * j;
        int buf = g >> 9;                 // 0:Ah 1:Al 2:W
        int cid = g & 511;
        int row = cid >> 2;
        int ch  = cid & 3;
        const __half* src = (buf == 0) ? Ah_g : (buf == 1) ? Al_g : W_g;
        int rbase = (buf < 2) ? bm : bn;
        cp_async16(base + buf * GA_BUF + row * GSTRIDE + ch * 16,
                   src + (size_t)(rbase + row) * DMODEL + k0 + ch * 8);
    }
}

__global__ __launch_bounds__(256, 2)
void gemm_mma_kernel(const float* __restrict__ b0, const float* __restrict__ b1,
                     const float* __restrict__ b2, float* __restrict__ Cout, int mode)
{
    extern __shared__ __align__(128) char smg[];
    const uint32_t sb = smem_u32(smg);
    const int tid = threadIdx.x;
    const int lane = tid & 31;
    const int wid = tid >> 5;
    const int wr = (wid >> 1) * 32;
    const int wn = (wid & 1) * 64;
    const int bm = blockIdx.y * 128;
    const int bn = blockIdx.x * 128;
    const int z = blockIdx.z;

    const int aslot = (mode == 0) ? z : 0;
    const int wslot = (mode == 0) ? z : 3;
    const __half* Ah_g = g_ah + (size_t)aslot * ACTN;
    const __half* Al_g = g_al + (size_t)aslot * ACTN;
    const __half* W_g  = g_w  + (size_t)wslot * WN;
    const float* bias = (mode == 1) ? b0 : (z == 0) ? b0 : (z == 1) ? b1 : b2;

    float acc[2][8][4];
#pragma unroll
    for (int a = 0; a < 2; a++)
#pragma unroll
        for (int b = 0; b < 8; b++)
#pragma unroll
            for (int c = 0; c < 4; c++) acc[a][b][c] = 0.f;

    g_load_stage(sb, 0, Ah_g, Al_g, W_g, bm, bn, 0, tid);   CP_COMMIT();
    g_load_stage(sb, 1, Ah_g, Al_g, W_g, bm, bn, GKC, tid); CP_COMMIT();

    const int NIT = DMODEL / GKC;   // 32
    const uint32_t a_row = (lane & 15);
    const uint32_t a_k8  = (lane >> 4) << 3;
    const uint32_t b_row = ((lane >> 4) << 3) + (lane & 7);
    const uint32_t b_k8  = ((lane >> 3) & 1) << 3;

    for (int it = 0; it < NIT; it++) {
        if (it == NIT - 1) { CP_WAIT(0); } else { CP_WAIT(1); }
        __syncthreads();

        if (it + 2 < NIT) {
            g_load_stage(sb, (it + 2) % GNSTG, Ah_g, Al_g, W_g, bm, bn,
                         (it + 2) * GKC, tid);
            CP_COMMIT();
        }

        uint32_t base = sb + (it % GNSTG) * GASTAGE;
#pragma unroll
        for (int ks = 0; ks < 2; ks++) {
            const int k0 = ks * 16;
            uint32_t Ah[2][4], Al[2][4], Bf[4][4];
#pragma unroll
            for (int mf = 0; mf < 2; mf++) {
                uint32_t ra = base + (wr + mf * 16 + a_row) * GSTRIDE + (k0 + a_k8) * 2;
                ldsm4(ra, Ah[mf]);
                ldsm4(ra + GA_BUF, Al[mf]);
            }
#pragma unroll
            for (int np = 0; np < 4; np++) {
                uint32_t rb = base + 2 * GA_BUF + (wn + np * 16 + b_row) * GSTRIDE
                              + (k0 + b_k8) * 2;
                ldsm4(rb, Bf[np]);
            }
#pragma unroll
            for (int np = 0; np < 4; np++)
#pragma unroll
                for (int nn = 0; nn < 2; nn++)
#pragma unroll
                    for (int mf = 0; mf < 2; mf++)
                        mma_f16(acc[mf][np * 2 + nn], Ah[mf], Bf[np] + 2 * nn);
#pragma unroll
            for (int np = 0; np < 4; np++)
#pragma unroll
                for (int nn = 0; nn < 2; nn++)
#pragma unroll
                    for (int mf = 0; mf < 2; mf++)
                        mma_f16(acc[mf][np * 2 + nn], Al[mf], Bf[np] + 2 * nn);
        }
    }

    // epilogue
    const float sc = (mode == 0 && z == 0) ? 0.125f : 1.0f;
#pragma unroll
    for (int mf = 0; mf < 2; mf++) {
#pragma unroll
        for (int nf = 0; nf < 8; nf++) {
            int r0 = bm + wr + mf * 16 + (lane >> 2);
            int c0 = bn + wn + nf * 8 + (lane & 3) * 2;
            float bs0 = bias[c0], bs1 = bias[c0 + 1];
#pragma unroll
            for (int hh = 0; hh < 2; hh++) {
                int row = r0 + 8 * hh;
                float v0 = (acc[mf][nf][2 * hh + 0] + bs0) * sc;
                float v1 = (acc[mf][nf][2 * hh + 1] + bs1) * sc;
                if (mode == 0) {
                    int hd = c0 >> 6, d = c0 & 63;
                    int b = row >> 11, s = row & (SEQ - 1);
                    size_t idx = ((((size_t)b * NHEAD + hd) * SEQ) + s) * DK + d;
                    if (z == 0) {
                        uint32_t hv, lv;
                        pack_hl(v0, v1, hv, lv);
                        *(uint32_t*)&g_qh[idx] = hv;
                        *(uint32_t*)&g_ql[idx] = lv;
                    } else if (z == 1) {
                        *(uint32_t*)&g_k[idx] = pack_h(v0, v1);
                    } else {
                        *(uint32_t*)&g_v[idx] = pack_h(v0, v1);
                    }
                } else {
                    float2 o = make_float2(v0, v1);
                    *(float2*)&Cout[(size_t)row * DMODEL + c0] = o;
                }
            }
        }
    }
}

// ---------------------------------------------------------------------------
// Flash attention: S = (Qh+Ql)K^T;  O = (Ph+Pl)·V  (P split in regs, V single).
// 3-buffer KV ring, prefetch depth 2, loads issued top-of-iter. 2 CTAs/SM.
// ---------------------------------------------------------------------------
#define ASTRIDE 144
#define AQBUF (128*ASTRIDE)          // 18432
#define AKBUF (64*ASTRIDE)           // 9216
#define ASTAGE (2*AKBUF)             // K, V = 18432
#define ANSTG 3
#define ATT_SMEM (2*AQBUF + ANSTG*ASTAGE)   // 92160

__device__ __forceinline__ void a_load_kv(uint32_t sb, int stg, int bh, int kt, int tid)
{
    uint32_t base = sb + 2 * AQBUF + stg * ASTAGE;
#pragma unroll
    for (int j = 0; j < 4; j++) {
        int g = tid + 256 * j;        // 0..1023
        int buf = g >> 9;             // 0:K 1:V
        int cid = g & 511;
        int row = cid >> 3;
        int ch  = cid & 7;
        const __half* src = buf ? g_v : g_k;
        const void* gp = src + ((size_t)bh * SEQ + kt * 64 + row) * DK + ch * 8;
        cp_async16(base + buf * AKBUF + row * ASTRIDE + ch * 16, gp);
    }
}

__global__ __launch_bounds__(256, 2)
void attn_mma_kernel()
{
    extern __shared__ __align__(128) char sma[];
    const uint32_t sb = smem_u32(sma);
    const int tid = threadIdx.x;
    const int lane = tid & 31;
    const int wid = tid >> 5;
    const int bh = blockIdx.y;
    const int q0 = blockIdx.x * 128;

    // Q tile hi/lo
#pragma unroll
    for (int j = 0; j < 8; j++) {
        int g = tid + 256 * j;
        int buf = g >> 10;           // 0:Qh 1:Ql
        int cid = g & 1023;
        int row = cid >> 3;
        int ch  = cid & 7;
        const __half* src = buf ? g_ql : g_qh;
        const void* gp = src + ((size_t)bh * SEQ + q0 + row) * DK + ch * 8;
        cp_async16(sb + buf * AQBUF + row * ASTRIDE + ch * 16, gp);
    }
    CP_COMMIT();
    a_load_kv(sb, 0, bh, 0, tid); CP_COMMIT();
    a_load_kv(sb, 1, bh, 1, tid); CP_COMMIT();

    const uint32_t a_row = (lane & 15);
    const uint32_t a_k8  = (lane >> 4) << 3;
    const uint32_t b_row = ((lane >> 4) << 3) + (lane & 7);
    const uint32_t b_k8  = ((lane >> 3) & 1) << 3;
    const uint32_t v_row = (((lane >> 3) & 1) << 3) + (lane & 7);
    const uint32_t v_c8  = (lane >> 4) << 3;
    const int wq = wid * 16;

    float o[8][4];
#pragma unroll
    for (int i = 0; i < 8; i++)
#pragma unroll
        for (int k = 0; k < 4; k++) o[i][k] = 0.f;
    float m0 = -INFINITY, m1 = -INFINITY, l0 = 0.f, l1 = 0.f;

    const int NT = SEQ / 64;   // 32
    for (int it = 0; it < NT; it++) {
        if (it == NT - 1) { CP_WAIT(0); } else { CP_WAIT(1); }
        __syncthreads();

        if (it + 2 < NT) {
            a_load_kv(sb, (it + 2) % ANSTG, bh, it + 2, tid);
            CP_COMMIT();
        }

        uint32_t kb = sb + 2 * AQBUF + (it % ANSTG) * ASTAGE;

        // ---- S = (Qh+Ql) K^T  (Q carries 1/8) ----
        float s[8][4];
#pragma unroll
        for (int i = 0; i < 8; i++)
#pragma unroll
            for (int k = 0; k < 4; k++) s[i][k] = 0.f;

#pragma unroll
        for (int ks = 0; ks < 4; ks++) {
            uint32_t ra = sb + (wq + a_row) * ASTRIDE + (ks * 16 + a_k8) * 2;
            uint32_t Qh[4], Ql[4];
            ldsm4(ra, Qh);
            ldsm4(ra + AQBUF, Ql);
#pragma unroll
            for (int np = 0; np < 4; np++) {
                uint32_t rb = kb + (np * 16 + b_row) * ASTRIDE + (ks * 16 + b_k8) * 2;
                uint32_t Kf[4];
                ldsm4(rb, Kf);
#pragma unroll
                for (int nn = 0; nn < 2; nn++)
                    mma_f16(s[np * 2 + nn], Qh, Kf + 2 * nn);
#pragma unroll
                for (int nn = 0; nn < 2; nn++)
                    mma_f16(s[np * 2 + nn], Ql, Kf + 2 * nn);
            }
        }

        // ---- online softmax ----
        float mx0 = -INFINITY, mx1 = -INFINITY;
#pragma unroll
        for (int i = 0; i < 8; i++) {
            mx0 = fmaxf(mx0, fmaxf(s[i][0], s[i][1]));
            mx1 = fmaxf(mx1, fmaxf(s[i][2], s[i][3]));
        }
        mx0 = fmaxf(mx0, __shfl_xor_sync(0xffffffffu, mx0, 1));
        mx0 = fmaxf(mx0, __shfl_xor_sync(0xffffffffu, mx0, 2));
        mx1 = fmaxf(mx1, __shfl_xor_sync(0xffffffffu, mx1, 1));
        mx1 = fmaxf(mx1, __shfl_xor_sync(0xffffffffu, mx1, 2));

        float mn0 = fmaxf(m0, mx0), mn1 = fmaxf(m1, mx1);
        float al0 = __expf(m0 - mn0), al1 = __expf(m1 - mn1);
        m0 = mn0; m1 = mn1;

        float rs0 = 0.f, rs1 = 0.f;
#pragma unroll
        for (int i = 0; i < 8; i++) {
            s[i][0] = __expf(s[i][0] - mn0);
            s[i][1] = __expf(s[i][1] - mn0);
            s[i][2] = __expf(s[i][2] - mn1);
            s[i][3] = __expf(s[i][3] - mn1);
            rs0 += s[i][0] + s[i][1];
            rs1 += s[i][2] + s[i][3];
        }
        rs0 += __shfl_xor_sync(0xffffffffu, rs0, 1);
        rs0 += __shfl_xor_sync(0xffffffffu, rs0, 2);
        rs1 += __shfl_xor_sync(0xffffffffu, rs1, 1);
        rs1 += __shfl_xor_sync(0xffffffffu, rs1, 2);
        l0 = l0 * al0 + rs0;
        l1 = l1 * al1 + rs1;
#pragma unroll
        for (int i = 0; i < 8; i++) {
            o[i][0] *= al0; o[i][1] *= al0;
            o[i][2] *= al1; o[i][3] *= al1;
        }

        // ---- O += (Ph+Pl) V  (P split per-j in registers, V single) ----
#pragma unroll
        for (int j = 0; j < 4; j++) {
            uint32_t Ph[4], Pl[4];
            pack_hl(s[2*j][0],   s[2*j][1],   Ph[0], Pl[0]);
            pack_hl(s[2*j][2],   s[2*j][3],   Ph[1], Pl[1]);
            pack_hl(s[2*j+1][0], s[2*j+1][1], Ph[2], Pl[2]);
            pack_hl(s[2*j+1][2], s[2*j+1][3], Ph[3], Pl[3]);
#pragma unroll
            for (int np = 0; np < 4; np++) {
                uint32_t rv = kb + AKBUF + (j * 16 + v_row) * ASTRIDE
                              + (np * 16 + v_c8) * 2;
                uint32_t Vf[4];
                ldsm4t(rv, Vf);
#pragma unroll
                for (int nn = 0; nn < 2; nn++)
                    mma_f16(o[np * 2 + nn], Ph, Vf + 2 * nn);
#pragma unroll
                for (int nn = 0; nn < 2; nn++)
                    mma_f16(o[np * 2 + nn], Pl, Vf + 2 * nn);
            }
        }
    }

    // ---- epilogue: x hi/lo into act slot 0 ----
    float inv0 = 1.0f / l0, inv1 = 1.0f / l1;
    const int b = bh >> 4;
    const int h = bh & (NHEAD - 1);
    const int qrow = q0 + wid * 16 + (lane >> 2);
#pragma unroll
    for (int nf = 0; nf < 8; nf++) {
        int d = h * DK + nf * 8 + (lane & 3) * 2;
        uint32_t hv, lv;
        size_t idx0 = ((size_t)b * SEQ + qrow) * DMODEL + d;
        pack_hl(o[nf][0] * inv0, o[nf][1] * inv0, hv, lv);
        *(uint32_t*)&g_ah[idx0] = hv;
        *(uint32_t*)&g_al[idx0] = lv;
        size_t idx1 = ((size_t)b * SEQ + qrow + 8) * DMODEL + d;
        pack_hl(o[nf][2] * inv1, o[nf][3] * inv1, hv, lv);
        *(uint32_t*)&g_ah[idx1] = hv;
        *(uint32_t*)&g_al[idx1] = lv;
    }
}

// ---------------------------------------------------------------------------
extern "C" void kernel_launch(void* const* d_in, const int* in_sizes, int n_in,
                              void* d_out, int out_size)
{
    (void)in_sizes; (void)n_in; (void)out_size;
    const float* query = (const float*)d_in[0];
    const float* key   = (const float*)d_in[1];
    const float* value = (const float*)d_in[2];
    const float* Wq = (const float*)d_in[3];
    const float* bq = (const float*)d_in[4];
    const float* Wk = (const float*)d_in[5];
    const float* bk = (const float*)d_in[6];
    const float* Wv = (const float*)d_in[7];
    const float* bv = (const float*)d_in[8];
    const float* Wo = (const float*)d_in[9];
    const float* bo = (const float*)d_in[10];
    float* out = (float*)d_out;

    cudaFuncSetAttribute(gemm_mma_kernel, cudaFuncAttributeMaxDynamicSharedMemorySize,
                         GEMM_SMEM);
    cudaFuncSetAttribute(attn_mma_kernel, cudaFuncAttributeMaxDynamicSharedMemorySize,
                         ATT_SMEM);

    const int nA4 = (int)(ACTN / 4);
    const int nW4 = (int)(WN / 4);

    cvt_w_kernel<<<dim3(nW4 / 256, 4), 256>>>(Wq, Wk, Wv, Wo, nW4);
    cvt_act_kernel<<<dim3(nA4 / 256, 3), 256>>>(query, key, value, nA4);

    gemm_mma_kernel<<<dim3(8, 64, 3), 256, GEMM_SMEM>>>(bq, bk, bv, nullptr, 0);

    attn_mma_kernel<<<dim3(SEQ / 128, BATCH * NHEAD), 256, ATT_SMEM>>>();

    gemm_mma_kernel<<<dim3(8, 64, 1), 256, GEMM_SMEM>>>(bo, bo, bo, out, 1);
}